// round 1
// baseline (speedup 1.0000x reference)
#include <cuda_runtime.h>
#include <math.h>

#define BATCH 16384
#define DIM   1024
#define NLAYERS 6

// ---- scratch (allocation-free: __device__ globals) ----
__device__ float g_h[(size_t)BATCH * DIM];     // current hidden state
__device__ float g_t[(size_t)BATCH * DIM];     // tanh(h@W1^T + b1)
__device__ float g_dirs[3 * DIM];              // normalized anchors e,c,n
__device__ float g_dn2[3];                     // ||dir||^2 (post-normalize, ~1)
__device__ float g_coef[(size_t)BATCH * 3];    // per-row ce, cc, cn

static __device__ __forceinline__ float dot4(const float4 a, const float4 b) {
    return a.x * b.x + a.y * b.y + a.z * b.z + a.w * b.w;
}

// ---------------------------------------------------------------------------
// Normalize the 3 anchors; also store ||dir||^2.
// grid = 3 blocks x 256 threads (each thread owns one float4 of the vector)
// ---------------------------------------------------------------------------
__global__ void anchor_kernel(const float* __restrict__ ae,
                              const float* __restrict__ ac,
                              const float* __restrict__ an) {
    const int b = blockIdx.x;
    const int t = threadIdx.x;
    const float* src = (b == 0) ? ae : ((b == 1) ? ac : an);
    float4 v = reinterpret_cast<const float4*>(src)[t];
    float s = dot4(v, v);
#pragma unroll
    for (int o = 16; o; o >>= 1) s += __shfl_down_sync(0xffffffffu, s, o);
    __shared__ float sh[8];
    if ((t & 31) == 0) sh[t >> 5] = s;
    __syncthreads();
    __shared__ float s_inv;
    if (t == 0) {
        float tot = 0.f;
#pragma unroll
        for (int i = 0; i < 8; ++i) tot += sh[i];
        s_inv = 1.0f / fmaxf(sqrtf(tot), 1e-12f);
    }
    __syncthreads();
    const float inv = s_inv;
    v.x *= inv; v.y *= inv; v.z *= inv; v.w *= inv;
    reinterpret_cast<float4*>(g_dirs + (size_t)b * DIM)[t] = v;

    // second reduction: ||dir||^2 (avoid assuming exactly 1)
    float s2 = dot4(v, v);
#pragma unroll
    for (int o = 16; o; o >>= 1) s2 += __shfl_down_sync(0xffffffffu, s2, o);
    __syncthreads();
    if ((t & 31) == 0) sh[t >> 5] = s2;
    __syncthreads();
    if (t == 0) {
        float tot = 0.f;
#pragma unroll
        for (int i = 0; i < 8; ++i) tot += sh[i];
        g_dn2[b] = tot;
    }
}

// ---------------------------------------------------------------------------
// Per-row prep: (optionally) apply previous layer's norm clamp, then compute
// the 3 update coefficients for this layer from one 4-way reduction.
// grid = BATCH blocks x 256 threads.
//   use_ext: read h from Hext (layer 0) and force-store into g_h.
//   do_clamp: apply ||h||>10 soft rescale before computing stats.
// ---------------------------------------------------------------------------
__global__ void prep_kernel(const float* __restrict__ Hext, int use_ext, int do_clamp) {
    const int row = blockIdx.x;
    const int t = threadIdx.x;
    const float* hrow = use_ext ? (Hext + (size_t)row * DIM) : (g_h + (size_t)row * DIM);
    float4 hv = reinterpret_cast<const float4*>(hrow)[t];
    const float4 ev = reinterpret_cast<const float4*>(g_dirs)[t];
    const float4 cv = reinterpret_cast<const float4*>(g_dirs + DIM)[t];
    const float4 nv = reinterpret_cast<const float4*>(g_dirs + 2 * DIM)[t];

    float s2 = dot4(hv, hv);
    float de = dot4(hv, ev);
    float dc = dot4(hv, cv);
    float dn = dot4(hv, nv);
#pragma unroll
    for (int o = 16; o; o >>= 1) {
        s2 += __shfl_down_sync(0xffffffffu, s2, o);
        de += __shfl_down_sync(0xffffffffu, de, o);
        dc += __shfl_down_sync(0xffffffffu, dc, o);
        dn += __shfl_down_sync(0xffffffffu, dn, o);
    }
    __shared__ float sh[8][4];
    if ((t & 31) == 0) {
        sh[t >> 5][0] = s2; sh[t >> 5][1] = de; sh[t >> 5][2] = dc; sh[t >> 5][3] = dn;
    }
    __syncthreads();
    __shared__ float s_scale;
    if (t == 0) {
        float S2 = 0.f, DE = 0.f, DC = 0.f, DN = 0.f;
#pragma unroll
        for (int w = 0; w < 8; ++w) { S2 += sh[w][0]; DE += sh[w][1]; DC += sh[w][2]; DN += sh[w][3]; }
        float scale = 1.0f;
        if (do_clamp) {
            float nrm = sqrtf(S2);
            if (nrm > 10.0f) scale = 10.0f / (nrm + 1e-8f);
        }
        S2 *= scale * scale; DE *= scale; DC *= scale; DN *= scale;
        const float hn = fmaxf(sqrtf(S2), 1e-12f);
        const float a_e = DE / hn, a_c = DC / hn, a_n = DN / hn;
        const float div_e = 1.0f - a_e, div_c = 1.0f - a_c, div_n = 1.0f - a_n;
        const float boundary = fminf(fmaxf(1.0f - fabsf(a_e - a_c), 0.0f), 1.0f);
        const float fe = fmaxf(sqrtf(fmaxf(S2 - 2.0f * DE + g_dn2[0], 0.0f)), 1e-12f);
        const float fc = fmaxf(sqrtf(fmaxf(S2 - 2.0f * DC + g_dn2[1], 0.0f)), 1e-12f);
        const float fn = fmaxf(sqrtf(fmaxf(S2 - 2.0f * DN + g_dn2[2], 0.0f)), 1e-12f);
        g_coef[(size_t)row * 3 + 0] = 0.1f  * div_e / fe;
        g_coef[(size_t)row * 3 + 1] = 0.1f  * div_c / fc;
        g_coef[(size_t)row * 3 + 2] = (0.05f * div_n + 0.05f * boundary) / fn;
        s_scale = scale;
    }
    __syncthreads();
    const float sc = s_scale;
    if (use_ext || sc != 1.0f) {
        hv.x *= sc; hv.y *= sc; hv.z *= sc; hv.w *= sc;
        reinterpret_cast<float4*>(g_h + (size_t)row * DIM)[t] = hv;
    }
}

// ---------------------------------------------------------------------------
// NT GEMM: C[M,N] = A[M,K] * W[N,K]^T  (M=16384, N=K=1024), fp32 SIMT.
// Tiles: 128x128x16, 256 threads, 8x8 microtile per thread.
// EPI=1: C(g_t) = tanh(g_h @ W1^T + b1)
// EPI=2: g_h    = fused collapse update from delta = g_t @ W2^T + b2
// ---------------------------------------------------------------------------
#define BM 128
#define BN 128
#define BK 16

template <int EPI>
__global__ __launch_bounds__(256, 2)
void gemm_kernel(const float* __restrict__ W, const float* __restrict__ bias) {
    const float* A = (EPI == 1) ? g_h : g_t;
    float*       C = (EPI == 1) ? g_t : g_h;

    __shared__ float As[BK][BM];
    __shared__ float Ws[BK][BN];

    const int t   = threadIdx.x;
    const int bn0 = blockIdx.x * BN;
    const int bm0 = blockIdx.y * BM;
    const int tx  = t & 15;      // 0..15 (N direction)
    const int ty  = t >> 4;      // 0..15 (M direction)
    const int lr  = t >> 2;      // 0..63 load row
    const int lc  = (t & 3) * 4; // 0,4,8,12 load k-offset

    const float* Ap = A + (size_t)(bm0 + lr) * DIM + lc;
    const float* Wp = W + (size_t)(bn0 + lr) * DIM + lc;

    float4 pa0 = *reinterpret_cast<const float4*>(Ap);
    float4 pa1 = *reinterpret_cast<const float4*>(Ap + (size_t)64 * DIM);
    float4 pw0 = *reinterpret_cast<const float4*>(Wp);
    float4 pw1 = *reinterpret_cast<const float4*>(Wp + (size_t)64 * DIM);

    float acc[8][8];
#pragma unroll
    for (int i = 0; i < 8; ++i)
#pragma unroll
        for (int j = 0; j < 8; ++j) acc[i][j] = 0.f;

    const int NST = DIM / BK; // 64
    for (int s = 0; s < NST; ++s) {
        As[lc + 0][lr]      = pa0.x; As[lc + 1][lr]      = pa0.y;
        As[lc + 2][lr]      = pa0.z; As[lc + 3][lr]      = pa0.w;
        As[lc + 0][lr + 64] = pa1.x; As[lc + 1][lr + 64] = pa1.y;
        As[lc + 2][lr + 64] = pa1.z; As[lc + 3][lr + 64] = pa1.w;
        Ws[lc + 0][lr]      = pw0.x; Ws[lc + 1][lr]      = pw0.y;
        Ws[lc + 2][lr]      = pw0.z; Ws[lc + 3][lr]      = pw0.w;
        Ws[lc + 0][lr + 64] = pw1.x; Ws[lc + 1][lr + 64] = pw1.y;
        Ws[lc + 2][lr + 64] = pw1.z; Ws[lc + 3][lr + 64] = pw1.w;
        __syncthreads();

        if (s + 1 < NST) {
            const int off = (s + 1) * BK;
            pa0 = *reinterpret_cast<const float4*>(Ap + off);
            pa1 = *reinterpret_cast<const float4*>(Ap + (size_t)64 * DIM + off);
            pw0 = *reinterpret_cast<const float4*>(Wp + off);
            pw1 = *reinterpret_cast<const float4*>(Wp + (size_t)64 * DIM + off);
        }

#pragma unroll
        for (int k = 0; k < BK; ++k) {
            float af[8], wf[8];
            *reinterpret_cast<float4*>(af)     = *reinterpret_cast<const float4*>(&As[k][ty * 8]);
            *reinterpret_cast<float4*>(af + 4) = *reinterpret_cast<const float4*>(&As[k][ty * 8 + 4]);
            *reinterpret_cast<float4*>(wf)     = *reinterpret_cast<const float4*>(&Ws[k][tx * 8]);
            *reinterpret_cast<float4*>(wf + 4) = *reinterpret_cast<const float4*>(&Ws[k][tx * 8 + 4]);
#pragma unroll
            for (int i = 0; i < 8; ++i)
#pragma unroll
                for (int j = 0; j < 8; ++j) acc[i][j] += af[i] * wf[j];
        }
        if (s + 1 < NST) __syncthreads();
    }

    const int c0 = bn0 + tx * 8;
    if (EPI == 1) {
#pragma unroll
        for (int i = 0; i < 8; ++i) {
            const int r = bm0 + ty * 8 + i;
            float* crow = C + (size_t)r * DIM + c0;
#pragma unroll
            for (int h = 0; h < 2; ++h) {
                const float4 bv = *reinterpret_cast<const float4*>(bias + c0 + h * 4);
                float4 o;
                o.x = tanhf(acc[i][h * 4 + 0] + bv.x);
                o.y = tanhf(acc[i][h * 4 + 1] + bv.y);
                o.z = tanhf(acc[i][h * 4 + 2] + bv.z);
                o.w = tanhf(acc[i][h * 4 + 3] + bv.w);
                *reinterpret_cast<float4*>(crow + h * 4) = o;
            }
        }
    } else {
#pragma unroll
        for (int i = 0; i < 8; ++i) {
            const int r = bm0 + ty * 8 + i;
            const float ce = g_coef[(size_t)r * 3 + 0];
            const float cc = g_coef[(size_t)r * 3 + 1];
            const float cn = g_coef[(size_t)r * 3 + 2];
            float* crow = C + (size_t)r * DIM + c0;
#pragma unroll
            for (int h = 0; h < 2; ++h) {
                const int c = c0 + h * 4;
                const float4 hv = *reinterpret_cast<const float4*>(crow + h * 4);
                const float4 ev = *reinterpret_cast<const float4*>(g_dirs + c);
                const float4 cv = *reinterpret_cast<const float4*>(g_dirs + DIM + c);
                const float4 nv = *reinterpret_cast<const float4*>(g_dirs + 2 * DIM + c);
                const float4 bv = *reinterpret_cast<const float4*>(bias + c);
                float4 o;
                o.x = hv.x + acc[i][h * 4 + 0] + bv.x - ce * (hv.x - ev.x) - cc * (hv.x - cv.x) - cn * (hv.x - nv.x);
                o.y = hv.y + acc[i][h * 4 + 1] + bv.y - ce * (hv.y - ev.y) - cc * (hv.y - cv.y) - cn * (hv.y - nv.y);
                o.z = hv.z + acc[i][h * 4 + 2] + bv.z - ce * (hv.z - ev.z) - cc * (hv.z - cv.z) - cn * (hv.z - nv.z);
                o.w = hv.w + acc[i][h * 4 + 3] + bv.w - ce * (hv.w - ev.w) - cc * (hv.w - cv.w) - cn * (hv.w - nv.w);
                *reinterpret_cast<float4*>(crow + h * 4) = o;
            }
        }
    }
}

// ---------------------------------------------------------------------------
// Final norm clamp, writing to d_out.
// ---------------------------------------------------------------------------
__global__ void final_kernel(float* __restrict__ out) {
    const int row = blockIdx.x;
    const int t = threadIdx.x;
    float4 hv = reinterpret_cast<const float4*>(g_h + (size_t)row * DIM)[t];
    float s2 = dot4(hv, hv);
#pragma unroll
    for (int o = 16; o; o >>= 1) s2 += __shfl_down_sync(0xffffffffu, s2, o);
    __shared__ float sh[8];
    if ((t & 31) == 0) sh[t >> 5] = s2;
    __syncthreads();
    __shared__ float s_scale;
    if (t == 0) {
        float tot = 0.f;
#pragma unroll
        for (int i = 0; i < 8; ++i) tot += sh[i];
        float nrm = sqrtf(tot);
        s_scale = (nrm > 10.0f) ? (10.0f / (nrm + 1e-8f)) : 1.0f;
    }
    __syncthreads();
    const float sc = s_scale;
    hv.x *= sc; hv.y *= sc; hv.z *= sc; hv.w *= sc;
    reinterpret_cast<float4*>(out + (size_t)row * DIM)[t] = hv;
}

extern "C" void kernel_launch(void* const* d_in, const int* in_sizes, int n_in,
                              void* d_out, int out_size) {
    (void)in_sizes; (void)n_in; (void)out_size;
    const float* h0 = (const float*)d_in[0];
    const float* W1 = (const float*)d_in[1];
    const float* b1 = (const float*)d_in[2];
    const float* W2 = (const float*)d_in[3];
    const float* b2 = (const float*)d_in[4];
    const float* ae = (const float*)d_in[5];
    const float* ac = (const float*)d_in[6];
    const float* an = (const float*)d_in[7];
    float* out = (float*)d_out;

    anchor_kernel<<<3, 256>>>(ae, ac, an);

    const dim3 ggrid(DIM / BN, BATCH / BM);
    for (int l = 0; l < NLAYERS; ++l) {
        if (l == 0)
            prep_kernel<<<BATCH, 256>>>(h0, /*use_ext=*/1, /*do_clamp=*/0);
        else
            prep_kernel<<<BATCH, 256>>>(nullptr, /*use_ext=*/0, /*do_clamp=*/1);
        gemm_kernel<1><<<ggrid, 256>>>(W1, b1);
        gemm_kernel<2><<<ggrid, 256>>>(W2, b2);
    }
    final_kernel<<<BATCH, 256>>>(out);
}

// round 3
// speedup vs baseline: 1.7561x; 1.7561x over previous
#include <cuda_runtime.h>
#include <cuda_bf16.h>
#include <math.h>

#define BATCH 16384
#define DIM   1024
#define NLAYERS 6

#define BM 128
#define BN 128
#define BK 32
#define ASTR 40   // smem row stride in bf16 elems (32 + 8 pad -> conflict-free)

// ---- scratch (allocation-free: __device__ globals; referenced ONLY in device code) ----
__device__ float g_h[(size_t)BATCH * DIM];             // hidden state (fp32)
__device__ __nv_bfloat16 g_th[(size_t)BATCH * DIM];    // tanh output, hi part
__device__ __nv_bfloat16 g_tl[(size_t)BATCH * DIM];    // tanh output, lo part
__device__ __nv_bfloat16 g_W1h[DIM * DIM], g_W1l[DIM * DIM];
__device__ __nv_bfloat16 g_W2h[DIM * DIM], g_W2l[DIM * DIM];
__device__ float g_dirs[3 * DIM];
__device__ float g_dn2[3];
__device__ float g_coef[(size_t)BATCH * 3];

static __device__ __forceinline__ float dot4(const float4 a, const float4 b) {
    return a.x * b.x + a.y * b.y + a.z * b.z + a.w * b.w;
}

static __device__ __forceinline__ void split2(float x, __nv_bfloat16& h, __nv_bfloat16& l) {
    h = __float2bfloat16(x);
    l = __float2bfloat16(x - __bfloat162float(h));
}

static __device__ __forceinline__ void mma16816(float* c, const unsigned* a, const unsigned* b) {
    asm volatile(
        "mma.sync.aligned.m16n8k16.row.col.f32.bf16.bf16.f32 "
        "{%0,%1,%2,%3}, {%4,%5,%6,%7}, {%8,%9}, {%0,%1,%2,%3};\n"
        : "+f"(c[0]), "+f"(c[1]), "+f"(c[2]), "+f"(c[3])
        : "r"(a[0]), "r"(a[1]), "r"(a[2]), "r"(a[3]), "r"(b[0]), "r"(b[1]));
}

// ---------------------------------------------------------------------------
// Split W1/W2 into bf16 hi/lo once (reused for all 6 layers).
// ---------------------------------------------------------------------------
__global__ void wsplit_kernel(const float* __restrict__ W1, const float* __restrict__ W2) {
    const size_t i = (size_t)blockIdx.x * 256 + threadIdx.x;
    float x = W1[i];
    split2(x, g_W1h[i], g_W1l[i]);
    x = W2[i];
    split2(x, g_W2h[i], g_W2l[i]);
}

// ---------------------------------------------------------------------------
// Normalize the 3 anchors; also store ||dir||^2.
// ---------------------------------------------------------------------------
__global__ void anchor_kernel(const float* __restrict__ ae,
                              const float* __restrict__ ac,
                              const float* __restrict__ an) {
    const int b = blockIdx.x;
    const int t = threadIdx.x;
    const float* src = (b == 0) ? ae : ((b == 1) ? ac : an);
    float4 v = reinterpret_cast<const float4*>(src)[t];
    float s = dot4(v, v);
#pragma unroll
    for (int o = 16; o; o >>= 1) s += __shfl_down_sync(0xffffffffu, s, o);
    __shared__ float sh[8];
    if ((t & 31) == 0) sh[t >> 5] = s;
    __syncthreads();
    __shared__ float s_inv;
    if (t == 0) {
        float tot = 0.f;
#pragma unroll
        for (int i = 0; i < 8; ++i) tot += sh[i];
        s_inv = 1.0f / fmaxf(sqrtf(tot), 1e-12f);
    }
    __syncthreads();
    const float inv = s_inv;
    v.x *= inv; v.y *= inv; v.z *= inv; v.w *= inv;
    reinterpret_cast<float4*>(g_dirs + (size_t)b * DIM)[t] = v;

    float s2 = dot4(v, v);
#pragma unroll
    for (int o = 16; o; o >>= 1) s2 += __shfl_down_sync(0xffffffffu, s2, o);
    __syncthreads();
    if ((t & 31) == 0) sh[t >> 5] = s2;
    __syncthreads();
    if (t == 0) {
        float tot = 0.f;
#pragma unroll
        for (int i = 0; i < 8; ++i) tot += sh[i];
        g_dn2[b] = tot;
    }
}

// ---------------------------------------------------------------------------
// Per-row prep: apply previous layer's norm clamp (if any) and compute the
// 3 collapse coefficients from one 4-way row reduction.
// ---------------------------------------------------------------------------
__global__ void prep_kernel(const float* __restrict__ Hext, int use_ext, int do_clamp) {
    const int row = blockIdx.x;
    const int t = threadIdx.x;
    const float* hrow = use_ext ? (Hext + (size_t)row * DIM) : (g_h + (size_t)row * DIM);
    float4 hv = reinterpret_cast<const float4*>(hrow)[t];
    const float4 ev = reinterpret_cast<const float4*>(g_dirs)[t];
    const float4 cv = reinterpret_cast<const float4*>(g_dirs + DIM)[t];
    const float4 nv = reinterpret_cast<const float4*>(g_dirs + 2 * DIM)[t];

    float s2 = dot4(hv, hv);
    float de = dot4(hv, ev);
    float dc = dot4(hv, cv);
    float dn = dot4(hv, nv);
#pragma unroll
    for (int o = 16; o; o >>= 1) {
        s2 += __shfl_down_sync(0xffffffffu, s2, o);
        de += __shfl_down_sync(0xffffffffu, de, o);
        dc += __shfl_down_sync(0xffffffffu, dc, o);
        dn += __shfl_down_sync(0xffffffffu, dn, o);
    }
    __shared__ float sh[8][4];
    if ((t & 31) == 0) {
        sh[t >> 5][0] = s2; sh[t >> 5][1] = de; sh[t >> 5][2] = dc; sh[t >> 5][3] = dn;
    }
    __syncthreads();
    __shared__ float s_scale;
    if (t == 0) {
        float S2 = 0.f, DE = 0.f, DC = 0.f, DN = 0.f;
#pragma unroll
        for (int w = 0; w < 8; ++w) { S2 += sh[w][0]; DE += sh[w][1]; DC += sh[w][2]; DN += sh[w][3]; }
        float scale = 1.0f;
        if (do_clamp) {
            float nrm = sqrtf(S2);
            if (nrm > 10.0f) scale = 10.0f / (nrm + 1e-8f);
        }
        S2 *= scale * scale; DE *= scale; DC *= scale; DN *= scale;
        const float hn = fmaxf(sqrtf(S2), 1e-12f);
        const float a_e = DE / hn, a_c = DC / hn, a_n = DN / hn;
        const float div_e = 1.0f - a_e, div_c = 1.0f - a_c, div_n = 1.0f - a_n;
        const float boundary = fminf(fmaxf(1.0f - fabsf(a_e - a_c), 0.0f), 1.0f);
        const float fe = fmaxf(sqrtf(fmaxf(S2 - 2.0f * DE + g_dn2[0], 0.0f)), 1e-12f);
        const float fc = fmaxf(sqrtf(fmaxf(S2 - 2.0f * DC + g_dn2[1], 0.0f)), 1e-12f);
        const float fn = fmaxf(sqrtf(fmaxf(S2 - 2.0f * DN + g_dn2[2], 0.0f)), 1e-12f);
        g_coef[(size_t)row * 3 + 0] = 0.1f  * div_e / fe;
        g_coef[(size_t)row * 3 + 1] = 0.1f  * div_c / fc;
        g_coef[(size_t)row * 3 + 2] = (0.05f * div_n + 0.05f * boundary) / fn;
        s_scale = scale;
    }
    __syncthreads();
    const float sc = s_scale;
    if (use_ext || sc != 1.0f) {
        hv.x *= sc; hv.y *= sc; hv.z *= sc; hv.w *= sc;
        reinterpret_cast<float4*>(g_h + (size_t)row * DIM)[t] = hv;
    }
}

// ---------------------------------------------------------------------------
// Tensor-core NT GEMM, bf16x3 split precision (hi*hi + hi*lo + lo*hi).
// C[M,N] = A[M,K] @ W[N,K]^T, M=16384, N=K=1024.
// 128x128x32 tiles, 256 threads (8 warps as 2x4), warp tile 64x32 via
// mma.sync.m16n8k16.
// EPI=1: A = g_h (fp32, split in-loop), W = g_W1h/l, writes split tanh to g_th/g_tl.
// EPI=2: A = g_th/g_tl, W = g_W2h/l, fused collapse epilogue writing fp32 g_h.
// Weight buffers are device globals referenced IN DEVICE CODE (never passed
// from host — host-side symbol addresses are invalid device pointers).
// ---------------------------------------------------------------------------
template <int EPI>
__global__ __launch_bounds__(256)
void gemm_kernel(const float* __restrict__ bias) {
    __shared__ __align__(16) __nv_bfloat16 Ah[BM * ASTR];
    __shared__ __align__(16) __nv_bfloat16 Al[BM * ASTR];
    __shared__ __align__(16) __nv_bfloat16 Bh[BN * ASTR];
    __shared__ __align__(16) __nv_bfloat16 Bl[BN * ASTR];

    const __nv_bfloat16* __restrict__ Wh = (EPI == 1) ? g_W1h : g_W2h;
    const __nv_bfloat16* __restrict__ Wl = (EPI == 1) ? g_W1l : g_W2l;

    const int tid  = threadIdx.x;
    const int lane = tid & 31;
    const int wid  = tid >> 5;
    const int wm   = wid >> 2;   // 0..1
    const int wn   = wid & 3;    // 0..3
    const int gid  = lane >> 2;  // 0..7
    const int t4   = lane & 3;   // 0..3
    const int bm0  = blockIdx.y * BM;
    const int bn0  = blockIdx.x * BN;
    const int lrow = tid >> 1;          // 0..127
    const int lcol = (tid & 1) * 16;    // 0 or 16

    const __nv_bfloat16* Whp = Wh + (size_t)(bn0 + lrow) * DIM + lcol;
    const __nv_bfloat16* Wlp = Wl + (size_t)(bn0 + lrow) * DIM + lcol;
    const float*         Afp = g_h  + (size_t)(bm0 + lrow) * DIM + lcol;
    const __nv_bfloat16* Ahp = g_th + (size_t)(bm0 + lrow) * DIM + lcol;
    const __nv_bfloat16* Alp = g_tl + (size_t)(bm0 + lrow) * DIM + lcol;

    float4 pa[4];
    uint4  pah[2], pal[2], pwh[2], pwl[2];
    if (EPI == 1) {
#pragma unroll
        for (int f = 0; f < 4; ++f) pa[f] = *reinterpret_cast<const float4*>(Afp + f * 4);
    } else {
        pah[0] = *reinterpret_cast<const uint4*>(Ahp);
        pah[1] = *reinterpret_cast<const uint4*>(Ahp + 8);
        pal[0] = *reinterpret_cast<const uint4*>(Alp);
        pal[1] = *reinterpret_cast<const uint4*>(Alp + 8);
    }
    pwh[0] = *reinterpret_cast<const uint4*>(Whp);
    pwh[1] = *reinterpret_cast<const uint4*>(Whp + 8);
    pwl[0] = *reinterpret_cast<const uint4*>(Wlp);
    pwl[1] = *reinterpret_cast<const uint4*>(Wlp + 8);

    float acc[4][4][4];
#pragma unroll
    for (int i = 0; i < 4; ++i)
#pragma unroll
        for (int j = 0; j < 4; ++j)
#pragma unroll
            for (int c = 0; c < 4; ++c) acc[i][j][c] = 0.f;

    const int sbase = lrow * ASTR + lcol;
    const int NST = DIM / BK;  // 32

    for (int s = 0; s < NST; ++s) {
        // ---- stage current tiles into smem ----
        if (EPI == 1) {
            __nv_bfloat16 hi[16], lo[16];
#pragma unroll
            for (int f = 0; f < 4; ++f) {
                split2(pa[f].x, hi[f * 4 + 0], lo[f * 4 + 0]);
                split2(pa[f].y, hi[f * 4 + 1], lo[f * 4 + 1]);
                split2(pa[f].z, hi[f * 4 + 2], lo[f * 4 + 2]);
                split2(pa[f].w, hi[f * 4 + 3], lo[f * 4 + 3]);
            }
            *reinterpret_cast<uint4*>(&Ah[sbase])     = *reinterpret_cast<uint4*>(hi);
            *reinterpret_cast<uint4*>(&Ah[sbase + 8]) = *reinterpret_cast<uint4*>(hi + 8);
            *reinterpret_cast<uint4*>(&Al[sbase])     = *reinterpret_cast<uint4*>(lo);
            *reinterpret_cast<uint4*>(&Al[sbase + 8]) = *reinterpret_cast<uint4*>(lo + 8);
        } else {
            *reinterpret_cast<uint4*>(&Ah[sbase])     = pah[0];
            *reinterpret_cast<uint4*>(&Ah[sbase + 8]) = pah[1];
            *reinterpret_cast<uint4*>(&Al[sbase])     = pal[0];
            *reinterpret_cast<uint4*>(&Al[sbase + 8]) = pal[1];
        }
        *reinterpret_cast<uint4*>(&Bh[sbase])     = pwh[0];
        *reinterpret_cast<uint4*>(&Bh[sbase + 8]) = pwh[1];
        *reinterpret_cast<uint4*>(&Bl[sbase])     = pwl[0];
        *reinterpret_cast<uint4*>(&Bl[sbase + 8]) = pwl[1];
        __syncthreads();

        // ---- prefetch next tiles ----
        if (s + 1 < NST) {
            const int off = (s + 1) * BK;
            if (EPI == 1) {
#pragma unroll
                for (int f = 0; f < 4; ++f)
                    pa[f] = *reinterpret_cast<const float4*>(Afp + off + f * 4);
            } else {
                pah[0] = *reinterpret_cast<const uint4*>(Ahp + off);
                pah[1] = *reinterpret_cast<const uint4*>(Ahp + off + 8);
                pal[0] = *reinterpret_cast<const uint4*>(Alp + off);
                pal[1] = *reinterpret_cast<const uint4*>(Alp + off + 8);
            }
            pwh[0] = *reinterpret_cast<const uint4*>(Whp + off);
            pwh[1] = *reinterpret_cast<const uint4*>(Whp + off + 8);
            pwl[0] = *reinterpret_cast<const uint4*>(Wlp + off);
            pwl[1] = *reinterpret_cast<const uint4*>(Wlp + off + 8);
        }

        // ---- compute: two k16 sub-steps ----
#pragma unroll
        for (int kk = 0; kk < 2; ++kk) {
            unsigned afh[4][4], afl[4][4], bfh[4][2], bfl[4][2];
#pragma unroll
            for (int mi = 0; mi < 4; ++mi) {
                const int rb = (wm * 64 + mi * 16 + gid) * ASTR + kk * 16 + t4 * 2;
                afh[mi][0] = *reinterpret_cast<const unsigned*>(&Ah[rb]);
                afh[mi][1] = *reinterpret_cast<const unsigned*>(&Ah[rb + 8 * ASTR]);
                afh[mi][2] = *reinterpret_cast<const unsigned*>(&Ah[rb + 8]);
                afh[mi][3] = *reinterpret_cast<const unsigned*>(&Ah[rb + 8 * ASTR + 8]);
                afl[mi][0] = *reinterpret_cast<const unsigned*>(&Al[rb]);
                afl[mi][1] = *reinterpret_cast<const unsigned*>(&Al[rb + 8 * ASTR]);
                afl[mi][2] = *reinterpret_cast<const unsigned*>(&Al[rb + 8]);
                afl[mi][3] = *reinterpret_cast<const unsigned*>(&Al[rb + 8 * ASTR + 8]);
            }
#pragma unroll
            for (int nj = 0; nj < 4; ++nj) {
                const int cb = (wn * 32 + nj * 8 + gid) * ASTR + kk * 16 + t4 * 2;
                bfh[nj][0] = *reinterpret_cast<const unsigned*>(&Bh[cb]);
                bfh[nj][1] = *reinterpret_cast<const unsigned*>(&Bh[cb + 8]);
                bfl[nj][0] = *reinterpret_cast<const unsigned*>(&Bl[cb]);
                bfl[nj][1] = *reinterpret_cast<const unsigned*>(&Bl[cb + 8]);
            }
#pragma unroll
            for (int mi = 0; mi < 4; ++mi)
#pragma unroll
                for (int nj = 0; nj < 4; ++nj) {
                    mma16816(acc[mi][nj], afh[mi], bfh[nj]);
                    mma16816(acc[mi][nj], afh[mi], bfl[nj]);
                    mma16816(acc[mi][nj], afl[mi], bfh[nj]);
                }
        }
        if (s + 1 < NST) __syncthreads();
    }

    // ---- epilogue ----
#pragma unroll
    for (int mi = 0; mi < 4; ++mi) {
#pragma unroll
        for (int rr = 0; rr < 2; ++rr) {
            const int r = bm0 + wm * 64 + mi * 16 + gid + rr * 8;
            if (EPI == 1) {
                __nv_bfloat16* th = g_th + (size_t)r * DIM;
                __nv_bfloat16* tl = g_tl + (size_t)r * DIM;
#pragma unroll
                for (int nj = 0; nj < 4; ++nj) {
                    const int col = bn0 + wn * 32 + nj * 8 + t4 * 2;
                    const float v0 = tanhf(acc[mi][nj][rr * 2 + 0] + bias[col]);
                    const float v1 = tanhf(acc[mi][nj][rr * 2 + 1] + bias[col + 1]);
                    __nv_bfloat162 h2, l2;
                    split2(v0, h2.x, l2.x);
                    split2(v1, h2.y, l2.y);
                    *reinterpret_cast<__nv_bfloat162*>(th + col) = h2;
                    *reinterpret_cast<__nv_bfloat162*>(tl + col) = l2;
                }
            } else {
                const float ce = g_coef[(size_t)r * 3 + 0];
                const float cc = g_coef[(size_t)r * 3 + 1];
                const float cn = g_coef[(size_t)r * 3 + 2];
                float* hrow = g_h + (size_t)r * DIM;
#pragma unroll
                for (int nj = 0; nj < 4; ++nj) {
                    const int col = bn0 + wn * 32 + nj * 8 + t4 * 2;
                    const float2 hv = *reinterpret_cast<const float2*>(hrow + col);
                    const float2 evv = *reinterpret_cast<const float2*>(g_dirs + col);
                    const float2 cvv = *reinterpret_cast<const float2*>(g_dirs + DIM + col);
                    const float2 nvv = *reinterpret_cast<const float2*>(g_dirs + 2 * DIM + col);
                    const float2 bv  = *reinterpret_cast<const float2*>(bias + col);
                    float2 o;
                    o.x = hv.x + acc[mi][nj][rr * 2 + 0] + bv.x
                        - ce * (hv.x - evv.x) - cc * (hv.x - cvv.x) - cn * (hv.x - nvv.x);
                    o.y = hv.y + acc[mi][nj][rr * 2 + 1] + bv.y
                        - ce * (hv.y - evv.y) - cc * (hv.y - cvv.y) - cn * (hv.y - nvv.y);
                    *reinterpret_cast<float2*>(hrow + col) = o;
                }
            }
        }
    }
}

// ---------------------------------------------------------------------------
// Final norm clamp, writing to d_out.
// ---------------------------------------------------------------------------
__global__ void final_kernel(float* __restrict__ out) {
    const int row = blockIdx.x;
    const int t = threadIdx.x;
    float4 hv = reinterpret_cast<const float4*>(g_h + (size_t)row * DIM)[t];
    float s2 = dot4(hv, hv);
#pragma unroll
    for (int o = 16; o; o >>= 1) s2 += __shfl_down_sync(0xffffffffu, s2, o);
    __shared__ float sh[8];
    if ((t & 31) == 0) sh[t >> 5] = s2;
    __syncthreads();
    __shared__ float s_scale;
    if (t == 0) {
        float tot = 0.f;
#pragma unroll
        for (int i = 0; i < 8; ++i) tot += sh[i];
        float nrm = sqrtf(tot);
        s_scale = (nrm > 10.0f) ? (10.0f / (nrm + 1e-8f)) : 1.0f;
    }
    __syncthreads();
    const float sc = s_scale;
    hv.x *= sc; hv.y *= sc; hv.z *= sc; hv.w *= sc;
    reinterpret_cast<float4*>(out + (size_t)row * DIM)[t] = hv;
}

extern "C" void kernel_launch(void* const* d_in, const int* in_sizes, int n_in,
                              void* d_out, int out_size) {
    (void)in_sizes; (void)n_in; (void)out_size;
    const float* h0 = (const float*)d_in[0];
    const float* W1 = (const float*)d_in[1];
    const float* b1 = (const float*)d_in[2];
    const float* W2 = (const float*)d_in[3];
    const float* b2 = (const float*)d_in[4];
    const float* ae = (const float*)d_in[5];
    const float* ac = (const float*)d_in[6];
    const float* an = (const float*)d_in[7];
    float* out = (float*)d_out;

    anchor_kernel<<<3, 256>>>(ae, ac, an);
    wsplit_kernel<<<DIM * DIM / 256, 256>>>(W1, W2);

    const dim3 ggrid(DIM / BN, BATCH / BM);
    for (int l = 0; l < NLAYERS; ++l) {
        if (l == 0)
            prep_kernel<<<BATCH, 256>>>(h0, /*use_ext=*/1, /*do_clamp=*/0);
        else
            prep_kernel<<<BATCH, 256>>>(nullptr, /*use_ext=*/0, /*do_clamp=*/1);
        gemm_kernel<1><<<ggrid, 256>>>(b1);
        gemm_kernel<2><<<ggrid, 256>>>(b2);
    }
    final_kernel<<<BATCH, 256>>>(out);
}

// round 5
// speedup vs baseline: 2.0395x; 1.1614x over previous
#include <cuda_runtime.h>
#include <cuda_bf16.h>
#include <math.h>

#define BATCH 16384
#define DIM   1024
#define NLAYERS 6

#define BM 128
#define BN 128
#define BK 32
#define ASTR 40            // smem row stride (bf16 elems): 32 + 8 pad, conflict-free
#define STAGES 3
#define TILE_ELEMS (BM * ASTR)          // 5120 bf16 per array
#define TILE_BYTES (TILE_ELEMS * 2)     // 10240 B
#define STAGE_BYTES (4 * TILE_BYTES)    // Ah, Al, Bh, Bl
#define SMEM_TOTAL_BYTES (STAGES * STAGE_BYTES)  // 122880 B

// ---- scratch (allocation-free: __device__ globals; device-code refs only) ----
__device__ float g_h[(size_t)BATCH * DIM];             // hidden state (fp32)
__device__ __nv_bfloat16 g_hh[(size_t)BATCH * DIM];    // h split hi
__device__ __nv_bfloat16 g_hl[(size_t)BATCH * DIM];    // h split lo
__device__ __nv_bfloat16 g_th[(size_t)BATCH * DIM];    // tanh split hi
__device__ __nv_bfloat16 g_tl[(size_t)BATCH * DIM];    // tanh split lo
__device__ __nv_bfloat16 g_W1h[DIM * DIM], g_W1l[DIM * DIM];
__device__ __nv_bfloat16 g_W2h[DIM * DIM], g_W2l[DIM * DIM];
__device__ float g_dirs[3 * DIM];
__device__ float g_dn2[3];
__device__ float g_coef[(size_t)BATCH * 3];

static __device__ __forceinline__ float dot4(const float4 a, const float4 b) {
    return a.x * b.x + a.y * b.y + a.z * b.z + a.w * b.w;
}

static __device__ __forceinline__ void split2(float x, __nv_bfloat16& h, __nv_bfloat16& l) {
    h = __float2bfloat16(x);
    l = __float2bfloat16(x - __bfloat162float(h));
}

static __device__ __forceinline__ void mma16816(float* c, const unsigned* a, const unsigned* b) {
    asm volatile(
        "mma.sync.aligned.m16n8k16.row.col.f32.bf16.bf16.f32 "
        "{%0,%1,%2,%3}, {%4,%5,%6,%7}, {%8,%9}, {%0,%1,%2,%3};\n"
        : "+f"(c[0]), "+f"(c[1]), "+f"(c[2]), "+f"(c[3])
        : "r"(a[0]), "r"(a[1]), "r"(a[2]), "r"(a[3]), "r"(b[0]), "r"(b[1]));
}

static __device__ __forceinline__ unsigned smem_u32(const void* p) {
    return (unsigned)__cvta_generic_to_shared(p);
}

static __device__ __forceinline__ void cp16(unsigned dst, const void* src) {
    asm volatile("cp.async.cg.shared.global [%0], [%1], 16;\n" :: "r"(dst), "l"(src));
}

static __device__ __forceinline__ void cp_commit() {
    asm volatile("cp.async.commit_group;\n");
}

template <int N>
static __device__ __forceinline__ void cp_wait() {
    asm volatile("cp.async.wait_group %0;\n" :: "n"(N));
}

// ---------------------------------------------------------------------------
// Split W1/W2 into bf16 hi/lo once (reused for all 6 layers).
// ---------------------------------------------------------------------------
__global__ void wsplit_kernel(const float* __restrict__ W1, const float* __restrict__ W2) {
    const size_t i = (size_t)blockIdx.x * 256 + threadIdx.x;
    float x = W1[i];
    split2(x, g_W1h[i], g_W1l[i]);
    x = W2[i];
    split2(x, g_W2h[i], g_W2l[i]);
}

// ---------------------------------------------------------------------------
// Normalize the 3 anchors; also store ||dir||^2.
// ---------------------------------------------------------------------------
__global__ void anchor_kernel(const float* __restrict__ ae,
                              const float* __restrict__ ac,
                              const float* __restrict__ an) {
    const int b = blockIdx.x;
    const int t = threadIdx.x;
    const float* src = (b == 0) ? ae : ((b == 1) ? ac : an);
    float4 v = reinterpret_cast<const float4*>(src)[t];
    float s = dot4(v, v);
#pragma unroll
    for (int o = 16; o; o >>= 1) s += __shfl_down_sync(0xffffffffu, s, o);
    __shared__ float sh[8];
    if ((t & 31) == 0) sh[t >> 5] = s;
    __syncthreads();
    __shared__ float s_inv;
    if (t == 0) {
        float tot = 0.f;
#pragma unroll
        for (int i = 0; i < 8; ++i) tot += sh[i];
        s_inv = 1.0f / fmaxf(sqrtf(tot), 1e-12f);
    }
    __syncthreads();
    const float inv = s_inv;
    v.x *= inv; v.y *= inv; v.z *= inv; v.w *= inv;
    reinterpret_cast<float4*>(g_dirs + (size_t)b * DIM)[t] = v;

    float s2 = dot4(v, v);
#pragma unroll
    for (int o = 16; o; o >>= 1) s2 += __shfl_down_sync(0xffffffffu, s2, o);
    __syncthreads();
    if ((t & 31) == 0) sh[t >> 5] = s2;
    __syncthreads();
    if (t == 0) {
        float tot = 0.f;
#pragma unroll
        for (int i = 0; i < 8; ++i) tot += sh[i];
        g_dn2[b] = tot;
    }
}

// ---------------------------------------------------------------------------
// Per-row prep: apply previous layer's norm clamp (if any), compute the 3
// collapse coefficients, and write the bf16 hi/lo split of h for GEMM1.
// ---------------------------------------------------------------------------
__global__ void prep_kernel(const float* __restrict__ Hext, int use_ext, int do_clamp) {
    const int row = blockIdx.x;
    const int t = threadIdx.x;
    const float* hrow = use_ext ? (Hext + (size_t)row * DIM) : (g_h + (size_t)row * DIM);
    float4 hv = reinterpret_cast<const float4*>(hrow)[t];
    const float4 ev = reinterpret_cast<const float4*>(g_dirs)[t];
    const float4 cv = reinterpret_cast<const float4*>(g_dirs + DIM)[t];
    const float4 nv = reinterpret_cast<const float4*>(g_dirs + 2 * DIM)[t];

    float s2 = dot4(hv, hv);
    float de = dot4(hv, ev);
    float dc = dot4(hv, cv);
    float dn = dot4(hv, nv);
#pragma unroll
    for (int o = 16; o; o >>= 1) {
        s2 += __shfl_down_sync(0xffffffffu, s2, o);
        de += __shfl_down_sync(0xffffffffu, de, o);
        dc += __shfl_down_sync(0xffffffffu, dc, o);
        dn += __shfl_down_sync(0xffffffffu, dn, o);
    }
    __shared__ float sh[8][4];
    if ((t & 31) == 0) {
        sh[t >> 5][0] = s2; sh[t >> 5][1] = de; sh[t >> 5][2] = dc; sh[t >> 5][3] = dn;
    }
    __syncthreads();
    __shared__ float s_scale;
    if (t == 0) {
        float S2 = 0.f, DE = 0.f, DC = 0.f, DN = 0.f;
#pragma unroll
        for (int w = 0; w < 8; ++w) { S2 += sh[w][0]; DE += sh[w][1]; DC += sh[w][2]; DN += sh[w][3]; }
        float scale = 1.0f;
        if (do_clamp) {
            float nrm = sqrtf(S2);
            if (nrm > 10.0f) scale = 10.0f / (nrm + 1e-8f);
        }
        S2 *= scale * scale; DE *= scale; DC *= scale; DN *= scale;
        const float hn = fmaxf(sqrtf(S2), 1e-12f);
        const float a_e = DE / hn, a_c = DC / hn, a_n = DN / hn;
        const float div_e = 1.0f - a_e, div_c = 1.0f - a_c, div_n = 1.0f - a_n;
        const float boundary = fminf(fmaxf(1.0f - fabsf(a_e - a_c), 0.0f), 1.0f);
        const float fe = fmaxf(sqrtf(fmaxf(S2 - 2.0f * DE + g_dn2[0], 0.0f)), 1e-12f);
        const float fc = fmaxf(sqrtf(fmaxf(S2 - 2.0f * DC + g_dn2[1], 0.0f)), 1e-12f);
        const float fn = fmaxf(sqrtf(fmaxf(S2 - 2.0f * DN + g_dn2[2], 0.0f)), 1e-12f);
        g_coef[(size_t)row * 3 + 0] = 0.1f  * div_e / fe;
        g_coef[(size_t)row * 3 + 1] = 0.1f  * div_c / fc;
        g_coef[(size_t)row * 3 + 2] = (0.05f * div_n + 0.05f * boundary) / fn;
        s_scale = scale;
    }
    __syncthreads();
    const float sc = s_scale;
    hv.x *= sc; hv.y *= sc; hv.z *= sc; hv.w *= sc;
    if (use_ext || sc != 1.0f)
        reinterpret_cast<float4*>(g_h + (size_t)row * DIM)[t] = hv;

    // bf16 hi/lo split of (scaled) h for GEMM1's A operand
    __nv_bfloat16 hh[4], hl[4];
    split2(hv.x, hh[0], hl[0]);
    split2(hv.y, hh[1], hl[1]);
    split2(hv.z, hh[2], hl[2]);
    split2(hv.w, hh[3], hl[3]);
    *reinterpret_cast<__nv_bfloat162*>(g_hh + (size_t)row * DIM + t * 4)     = *reinterpret_cast<__nv_bfloat162*>(hh);
    *reinterpret_cast<__nv_bfloat162*>(g_hh + (size_t)row * DIM + t * 4 + 2) = *reinterpret_cast<__nv_bfloat162*>(hh + 2);
    *reinterpret_cast<__nv_bfloat162*>(g_hl + (size_t)row * DIM + t * 4)     = *reinterpret_cast<__nv_bfloat162*>(hl);
    *reinterpret_cast<__nv_bfloat162*>(g_hl + (size_t)row * DIM + t * 4 + 2) = *reinterpret_cast<__nv_bfloat162*>(hl + 2);
}

// ---------------------------------------------------------------------------
// Tensor-core NT GEMM, bf16x3 (hi*hi + hi*lo + lo*hi), cp.async 3-stage
// pipeline. C[M,N] = A[M,K] @ W[N,K]^T, M=16384, N=K=1024.
// 128x128x32 tiles, 256 threads (8 warps, 2x4), warp tile 64x32, m16n8k16.
// EPI=1: A = g_hh/g_hl, W = W1, epilogue writes split tanh to g_th/g_tl.
// EPI=2: A = g_th/g_tl, W = W2, fused collapse epilogue writes fp32 g_h.
// ---------------------------------------------------------------------------
template <int EPI>
__global__ __launch_bounds__(256)
void gemm_kernel(const float* __restrict__ bias) {
    extern __shared__ __align__(16) __nv_bfloat16 smem[];

    const __nv_bfloat16* __restrict__ Wh = (EPI == 1) ? g_W1h : g_W2h;
    const __nv_bfloat16* __restrict__ Wl = (EPI == 1) ? g_W1l : g_W2l;
    const __nv_bfloat16* __restrict__ Ah_g = (EPI == 1) ? g_hh : g_th;
    const __nv_bfloat16* __restrict__ Al_g = (EPI == 1) ? g_hl : g_tl;

    const int tid  = threadIdx.x;
    const int lane = tid & 31;
    const int wid  = tid >> 5;
    const int wm   = wid >> 2;   // 0..1
    const int wn   = wid & 3;    // 0..3
    const int gid  = lane >> 2;  // 0..7
    const int t4   = lane & 3;   // 0..3
    const int bm0  = blockIdx.y * BM;
    const int bn0  = blockIdx.x * BN;

    // cp.async mapping: each thread copies two 16B chunks per array per stage.
    const int cr0 = tid >> 2;          // rows tid>>2 and 64+(tid>>2)
    const int cc0 = (tid & 3) * 8;     // bf16 col offset of 16B chunk

    const __nv_bfloat16* gAh0 = Ah_g + (size_t)(bm0 + cr0) * DIM + cc0;
    const __nv_bfloat16* gAl0 = Al_g + (size_t)(bm0 + cr0) * DIM + cc0;
    const __nv_bfloat16* gWh0 = Wh   + (size_t)(bn0 + cr0) * DIM + cc0;
    const __nv_bfloat16* gWl0 = Wl   + (size_t)(bn0 + cr0) * DIM + cc0;
    const size_t rstep = (size_t)64 * DIM;

    const unsigned s_base = smem_u32(smem);
    const unsigned s_off0 = (unsigned)(cr0 * ASTR + cc0) * 2u;
    const unsigned s_off1 = s_off0 + (unsigned)(64 * ASTR) * 2u;

    auto issue_stage = [&](int s) {
        const unsigned sb = s_base + (unsigned)((s % STAGES) * STAGE_BYTES);
        const int ko = s * BK;
        cp16(sb + s_off0,                  gAh0 + ko);
        cp16(sb + s_off1,                  gAh0 + rstep + ko);
        cp16(sb + TILE_BYTES + s_off0,     gAl0 + ko);
        cp16(sb + TILE_BYTES + s_off1,     gAl0 + rstep + ko);
        cp16(sb + 2 * TILE_BYTES + s_off0, gWh0 + ko);
        cp16(sb + 2 * TILE_BYTES + s_off1, gWh0 + rstep + ko);
        cp16(sb + 3 * TILE_BYTES + s_off0, gWl0 + ko);
        cp16(sb + 3 * TILE_BYTES + s_off1, gWl0 + rstep + ko);
    };

    float acc[4][4][4];
#pragma unroll
    for (int i = 0; i < 4; ++i)
#pragma unroll
        for (int j = 0; j < 4; ++j)
#pragma unroll
            for (int c = 0; c < 4; ++c) acc[i][j][c] = 0.f;

    const int NST = DIM / BK;  // 32

    // prologue: stages 0..STAGES-2 in flight
#pragma unroll
    for (int s = 0; s < STAGES - 1; ++s) {
        issue_stage(s);
        cp_commit();
    }

    for (int s = 0; s < NST; ++s) {
        if (s + STAGES - 1 < NST) issue_stage(s + STAGES - 1);
        cp_commit();                 // exactly one group per iteration
        cp_wait<STAGES - 1>();       // stage s data resident
        __syncthreads();             // all threads see stage s; buffer (s) free of readers below

        const __nv_bfloat16* Ah = smem + (size_t)(s % STAGES) * (STAGE_BYTES / 2);
        const __nv_bfloat16* Al = Ah + TILE_ELEMS;
        const __nv_bfloat16* Bh = Ah + 2 * TILE_ELEMS;
        const __nv_bfloat16* Bl = Ah + 3 * TILE_ELEMS;

#pragma unroll
        for (int kk = 0; kk < 2; ++kk) {
            unsigned afh[4][4], afl[4][4], bfh[4][2], bfl[4][2];
#pragma unroll
            for (int mi = 0; mi < 4; ++mi) {
                const int rb = (wm * 64 + mi * 16 + gid) * ASTR + kk * 16 + t4 * 2;
                afh[mi][0] = *reinterpret_cast<const unsigned*>(&Ah[rb]);
                afh[mi][1] = *reinterpret_cast<const unsigned*>(&Ah[rb + 8 * ASTR]);
                afh[mi][2] = *reinterpret_cast<const unsigned*>(&Ah[rb + 8]);
                afh[mi][3] = *reinterpret_cast<const unsigned*>(&Ah[rb + 8 * ASTR + 8]);
                afl[mi][0] = *reinterpret_cast<const unsigned*>(&Al[rb]);
                afl[mi][1] = *reinterpret_cast<const unsigned*>(&Al[rb + 8 * ASTR]);
                afl[mi][2] = *reinterpret_cast<const unsigned*>(&Al[rb + 8]);
                afl[mi][3] = *reinterpret_cast<const unsigned*>(&Al[rb + 8 * ASTR + 8]);
            }
#pragma unroll
            for (int nj = 0; nj < 4; ++nj) {
                const int cb = (wn * 32 + nj * 8 + gid) * ASTR + kk * 16 + t4 * 2;
                bfh[nj][0] = *reinterpret_cast<const unsigned*>(&Bh[cb]);
                bfh[nj][1] = *reinterpret_cast<const unsigned*>(&Bh[cb + 8]);
                bfl[nj][0] = *reinterpret_cast<const unsigned*>(&Bl[cb]);
                bfl[nj][1] = *reinterpret_cast<const unsigned*>(&Bl[cb + 8]);
            }
#pragma unroll
            for (int mi = 0; mi < 4; ++mi)
#pragma unroll
                for (int nj = 0; nj < 4; ++nj) {
                    mma16816(acc[mi][nj], afh[mi], bfh[nj]);
                    mma16816(acc[mi][nj], afh[mi], bfl[nj]);
                    mma16816(acc[mi][nj], afl[mi], bfh[nj]);
                }
        }
        if (s + 1 < NST) __syncthreads();   // reads of stage s done before it is re-filled
    }

    // ---- epilogue ----
#pragma unroll
    for (int mi = 0; mi < 4; ++mi) {
#pragma unroll
        for (int rr = 0; rr < 2; ++rr) {
            const int r = bm0 + wm * 64 + mi * 16 + gid + rr * 8;
            if (EPI == 1) {
                __nv_bfloat16* th = g_th + (size_t)r * DIM;
                __nv_bfloat16* tl = g_tl + (size_t)r * DIM;
#pragma unroll
                for (int nj = 0; nj < 4; ++nj) {
                    const int col = bn0 + wn * 32 + nj * 8 + t4 * 2;
                    const float v0 = tanhf(acc[mi][nj][rr * 2 + 0] + bias[col]);
                    const float v1 = tanhf(acc[mi][nj][rr * 2 + 1] + bias[col + 1]);
                    __nv_bfloat162 h2, l2;
                    split2(v0, h2.x, l2.x);
                    split2(v1, h2.y, l2.y);
                    *reinterpret_cast<__nv_bfloat162*>(th + col) = h2;
                    *reinterpret_cast<__nv_bfloat162*>(tl + col) = l2;
                }
            } else {
                const float ce = g_coef[(size_t)r * 3 + 0];
                const float cc = g_coef[(size_t)r * 3 + 1];
                const float cn = g_coef[(size_t)r * 3 + 2];
                float* hrow = g_h + (size_t)r * DIM;
#pragma unroll
                for (int nj = 0; nj < 4; ++nj) {
                    const int col = bn0 + wn * 32 + nj * 8 + t4 * 2;
                    const float2 hv = *reinterpret_cast<const float2*>(hrow + col);
                    const float2 evv = *reinterpret_cast<const float2*>(g_dirs + col);
                    const float2 cvv = *reinterpret_cast<const float2*>(g_dirs + DIM + col);
                    const float2 nvv = *reinterpret_cast<const float2*>(g_dirs + 2 * DIM + col);
                    const float2 bv  = *reinterpret_cast<const float2*>(bias + col);
                    float2 o;
                    o.x = hv.x + acc[mi][nj][rr * 2 + 0] + bv.x
                        - ce * (hv.x - evv.x) - cc * (hv.x - cvv.x) - cn * (hv.x - nvv.x);
                    o.y = hv.y + acc[mi][nj][rr * 2 + 1] + bv.y
                        - ce * (hv.y - evv.y) - cc * (hv.y - cvv.y) - cn * (hv.y - nvv.y);
                    *reinterpret_cast<float2*>(hrow + col) = o;
                }
            }
        }
    }
}

// ---------------------------------------------------------------------------
// Final norm clamp, writing to d_out.
// ---------------------------------------------------------------------------
__global__ void final_kernel(float* __restrict__ out) {
    const int row = blockIdx.x;
    const int t = threadIdx.x;
    float4 hv = reinterpret_cast<const float4*>(g_h + (size_t)row * DIM)[t];
    float s2 = dot4(hv, hv);
#pragma unroll
    for (int o = 16; o; o >>= 1) s2 += __shfl_down_sync(0xffffffffu, s2, o);
    __shared__ float sh[8];
    if ((t & 31) == 0) sh[t >> 5] = s2;
    __syncthreads();
    __shared__ float s_scale;
    if (t == 0) {
        float tot = 0.f;
#pragma unroll
        for (int i = 0; i < 8; ++i) tot += sh[i];
        float nrm = sqrtf(tot);
        s_scale = (nrm > 10.0f) ? (10.0f / (nrm + 1e-8f)) : 1.0f;
    }
    __syncthreads();
    const float sc = s_scale;
    hv.x *= sc; hv.y *= sc; hv.z *= sc; hv.w *= sc;
    reinterpret_cast<float4*>(out + (size_t)row * DIM)[t] = hv;
}

extern "C" void kernel_launch(void* const* d_in, const int* in_sizes, int n_in,
                              void* d_out, int out_size) {
    (void)in_sizes; (void)n_in; (void)out_size;
    const float* h0 = (const float*)d_in[0];
    const float* W1 = (const float*)d_in[1];
    const float* b1 = (const float*)d_in[2];
    const float* W2 = (const float*)d_in[3];
    const float* b2 = (const float*)d_in[4];
    const float* ae = (const float*)d_in[5];
    const float* ac = (const float*)d_in[6];
    const float* an = (const float*)d_in[7];
    float* out = (float*)d_out;

    // Raise dynamic smem limit once (non-stream API; done before any launch,
    // so captured and non-captured calls execute an identical launch sequence).
    static bool s_attr_done = false;
    if (!s_attr_done) {
        cudaFuncSetAttribute(gemm_kernel<1>, cudaFuncAttributeMaxDynamicSharedMemorySize, SMEM_TOTAL_BYTES);
        cudaFuncSetAttribute(gemm_kernel<2>, cudaFuncAttributeMaxDynamicSharedMemorySize, SMEM_TOTAL_BYTES);
        s_attr_done = true;
    }

    anchor_kernel<<<3, 256>>>(ae, ac, an);
    wsplit_kernel<<<DIM * DIM / 256, 256>>>(W1, W2);

    const dim3 ggrid(DIM / BN, BATCH / BM);
    for (int l = 0; l < NLAYERS; ++l) {
        if (l == 0)
            prep_kernel<<<BATCH, 256>>>(h0, /*use_ext=*/1, /*do_clamp=*/0);
        else
            prep_kernel<<<BATCH, 256>>>(nullptr, /*use_ext=*/0, /*do_clamp=*/1);
        gemm_kernel<1><<<ggrid, 256, SMEM_TOTAL_BYTES>>>(b1);
        gemm_kernel<2><<<ggrid, 256, SMEM_TOTAL_BYTES>>>(b2);
    }
    final_kernel<<<BATCH, 256>>>(out);
}

// round 6
// speedup vs baseline: 2.2706x; 1.1133x over previous
#include <cuda_runtime.h>
#include <cuda_bf16.h>
#include <math.h>

#define BATCH 16384
#define DIM   1024
#define NLAYERS 6

#define BM 128
#define BN 128
#define BK 32
#define ASTR 40            // smem row stride (bf16 elems): 32 + 8 pad, conflict-free
#define STAGES 2
#define TILE_ELEMS (BM * ASTR)          // 5120 bf16 per array
#define TILE_BYTES (TILE_ELEMS * 2)     // 10240 B
#define STAGE_BYTES (4 * TILE_BYTES)    // Ah, Al, Bh, Bl
#define SMEM_TOTAL_BYTES (STAGES * STAGE_BYTES)  // 81920 B -> 2 CTAs/SM

// ---- scratch (allocation-free: __device__ globals; device-code refs only) ----
__device__ float g_h[(size_t)BATCH * DIM];             // hidden state (fp32)
__device__ __nv_bfloat16 g_hh[(size_t)BATCH * DIM];    // h split hi
__device__ __nv_bfloat16 g_hl[(size_t)BATCH * DIM];    // h split lo
__device__ __nv_bfloat16 g_th[(size_t)BATCH * DIM];    // tanh split hi
__device__ __nv_bfloat16 g_tl[(size_t)BATCH * DIM];    // tanh split lo
__device__ __nv_bfloat16 g_W1h[DIM * DIM], g_W1l[DIM * DIM];
__device__ __nv_bfloat16 g_W2h[DIM * DIM], g_W2l[DIM * DIM];
__device__ float g_dirs[3 * DIM];
__device__ float g_dn2[3];
__device__ float g_coef[(size_t)BATCH * 3];

static __device__ __forceinline__ float dot4(const float4 a, const float4 b) {
    return a.x * b.x + a.y * b.y + a.z * b.z + a.w * b.w;
}

static __device__ __forceinline__ void split2(float x, __nv_bfloat16& h, __nv_bfloat16& l) {
    h = __float2bfloat16(x);
    l = __float2bfloat16(x - __bfloat162float(h));
}

static __device__ __forceinline__ void mma16816(float* c, const unsigned* a, const unsigned* b) {
    asm volatile(
        "mma.sync.aligned.m16n8k16.row.col.f32.bf16.bf16.f32 "
        "{%0,%1,%2,%3}, {%4,%5,%6,%7}, {%8,%9}, {%0,%1,%2,%3};\n"
        : "+f"(c[0]), "+f"(c[1]), "+f"(c[2]), "+f"(c[3])
        : "r"(a[0]), "r"(a[1]), "r"(a[2]), "r"(a[3]), "r"(b[0]), "r"(b[1]));
}

static __device__ __forceinline__ unsigned smem_u32(const void* p) {
    return (unsigned)__cvta_generic_to_shared(p);
}

static __device__ __forceinline__ void cp16(unsigned dst, const void* src) {
    asm volatile("cp.async.cg.shared.global [%0], [%1], 16;\n" :: "r"(dst), "l"(src));
}

static __device__ __forceinline__ void cp_commit() {
    asm volatile("cp.async.commit_group;\n");
}

template <int N>
static __device__ __forceinline__ void cp_wait() {
    asm volatile("cp.async.wait_group %0;\n" :: "n"(N));
}

// ---------------------------------------------------------------------------
// Split W1/W2 into bf16 hi/lo once (reused for all 6 layers).
// ---------------------------------------------------------------------------
__global__ void wsplit_kernel(const float* __restrict__ W1, const float* __restrict__ W2) {
    const size_t i = (size_t)blockIdx.x * 256 + threadIdx.x;
    float x = W1[i];
    split2(x, g_W1h[i], g_W1l[i]);
    x = W2[i];
    split2(x, g_W2h[i], g_W2l[i]);
}

// ---------------------------------------------------------------------------
// Normalize the 3 anchors; also store ||dir||^2.
// ---------------------------------------------------------------------------
__global__ void anchor_kernel(const float* __restrict__ ae,
                              const float* __restrict__ ac,
                              const float* __restrict__ an) {
    const int b = blockIdx.x;
    const int t = threadIdx.x;
    const float* src = (b == 0) ? ae : ((b == 1) ? ac : an);
    float4 v = reinterpret_cast<const float4*>(src)[t];
    float s = dot4(v, v);
#pragma unroll
    for (int o = 16; o; o >>= 1) s += __shfl_down_sync(0xffffffffu, s, o);
    __shared__ float sh[8];
    if ((t & 31) == 0) sh[t >> 5] = s;
    __syncthreads();
    __shared__ float s_inv;
    if (t == 0) {
        float tot = 0.f;
#pragma unroll
        for (int i = 0; i < 8; ++i) tot += sh[i];
        s_inv = 1.0f / fmaxf(sqrtf(tot), 1e-12f);
    }
    __syncthreads();
    const float inv = s_inv;
    v.x *= inv; v.y *= inv; v.z *= inv; v.w *= inv;
    reinterpret_cast<float4*>(g_dirs + (size_t)b * DIM)[t] = v;

    float s2 = dot4(v, v);
#pragma unroll
    for (int o = 16; o; o >>= 1) s2 += __shfl_down_sync(0xffffffffu, s2, o);
    __syncthreads();
    if ((t & 31) == 0) sh[t >> 5] = s2;
    __syncthreads();
    if (t == 0) {
        float tot = 0.f;
#pragma unroll
        for (int i = 0; i < 8; ++i) tot += sh[i];
        g_dn2[b] = tot;
    }
}

// ---------------------------------------------------------------------------
// Per-row prep: apply previous layer's norm clamp (if any), compute the 3
// collapse coefficients, and write the bf16 hi/lo split of h for GEMM1.
// ---------------------------------------------------------------------------
__global__ void prep_kernel(const float* __restrict__ Hext, int use_ext, int do_clamp) {
    const int row = blockIdx.x;
    const int t = threadIdx.x;
    const float* hrow = use_ext ? (Hext + (size_t)row * DIM) : (g_h + (size_t)row * DIM);
    float4 hv = reinterpret_cast<const float4*>(hrow)[t];
    const float4 ev = reinterpret_cast<const float4*>(g_dirs)[t];
    const float4 cv = reinterpret_cast<const float4*>(g_dirs + DIM)[t];
    const float4 nv = reinterpret_cast<const float4*>(g_dirs + 2 * DIM)[t];

    float s2 = dot4(hv, hv);
    float de = dot4(hv, ev);
    float dc = dot4(hv, cv);
    float dn = dot4(hv, nv);
#pragma unroll
    for (int o = 16; o; o >>= 1) {
        s2 += __shfl_down_sync(0xffffffffu, s2, o);
        de += __shfl_down_sync(0xffffffffu, de, o);
        dc += __shfl_down_sync(0xffffffffu, dc, o);
        dn += __shfl_down_sync(0xffffffffu, dn, o);
    }
    __shared__ float sh[8][4];
    if ((t & 31) == 0) {
        sh[t >> 5][0] = s2; sh[t >> 5][1] = de; sh[t >> 5][2] = dc; sh[t >> 5][3] = dn;
    }
    __syncthreads();
    __shared__ float s_scale;
    if (t == 0) {
        float S2 = 0.f, DE = 0.f, DC = 0.f, DN = 0.f;
#pragma unroll
        for (int w = 0; w < 8; ++w) { S2 += sh[w][0]; DE += sh[w][1]; DC += sh[w][2]; DN += sh[w][3]; }
        float scale = 1.0f;
        if (do_clamp) {
            float nrm = sqrtf(S2);
            if (nrm > 10.0f) scale = 10.0f / (nrm + 1e-8f);
        }
        S2 *= scale * scale; DE *= scale; DC *= scale; DN *= scale;
        const float hn = fmaxf(sqrtf(S2), 1e-12f);
        const float a_e = DE / hn, a_c = DC / hn, a_n = DN / hn;
        const float div_e = 1.0f - a_e, div_c = 1.0f - a_c, div_n = 1.0f - a_n;
        const float boundary = fminf(fmaxf(1.0f - fabsf(a_e - a_c), 0.0f), 1.0f);
        const float fe = fmaxf(sqrtf(fmaxf(S2 - 2.0f * DE + g_dn2[0], 0.0f)), 1e-12f);
        const float fc = fmaxf(sqrtf(fmaxf(S2 - 2.0f * DC + g_dn2[1], 0.0f)), 1e-12f);
        const float fn = fmaxf(sqrtf(fmaxf(S2 - 2.0f * DN + g_dn2[2], 0.0f)), 1e-12f);
        g_coef[(size_t)row * 3 + 0] = 0.1f  * div_e / fe;
        g_coef[(size_t)row * 3 + 1] = 0.1f  * div_c / fc;
        g_coef[(size_t)row * 3 + 2] = (0.05f * div_n + 0.05f * boundary) / fn;
        s_scale = scale;
    }
    __syncthreads();
    const float sc = s_scale;
    hv.x *= sc; hv.y *= sc; hv.z *= sc; hv.w *= sc;
    if (use_ext || sc != 1.0f)
        reinterpret_cast<float4*>(g_h + (size_t)row * DIM)[t] = hv;

    // bf16 hi/lo split of (scaled) h for GEMM1's A operand
    __nv_bfloat16 hh[4], hl[4];
    split2(hv.x, hh[0], hl[0]);
    split2(hv.y, hh[1], hl[1]);
    split2(hv.z, hh[2], hl[2]);
    split2(hv.w, hh[3], hl[3]);
    *reinterpret_cast<__nv_bfloat162*>(g_hh + (size_t)row * DIM + t * 4)     = *reinterpret_cast<__nv_bfloat162*>(hh);
    *reinterpret_cast<__nv_bfloat162*>(g_hh + (size_t)row * DIM + t * 4 + 2) = *reinterpret_cast<__nv_bfloat162*>(hh + 2);
    *reinterpret_cast<__nv_bfloat162*>(g_hl + (size_t)row * DIM + t * 4)     = *reinterpret_cast<__nv_bfloat162*>(hl);
    *reinterpret_cast<__nv_bfloat162*>(g_hl + (size_t)row * DIM + t * 4 + 2) = *reinterpret_cast<__nv_bfloat162*>(hl + 2);
}

// ---------------------------------------------------------------------------
// Tensor-core NT GEMM, bf16x3 (hi*hi + hi*lo + lo*hi), cp.async 2-stage
// pipeline, 2 CTAs/SM. C[M,N] = A[M,K] @ W[N,K]^T, M=16384, N=K=1024.
// 128x128x32 tiles, 256 threads (8 warps, 2x4), warp tile 64x32, m16n8k16.
// EPI=1: A = g_hh/g_hl, W = W1, epilogue writes split tanh to g_th/g_tl.
// EPI=2: A = g_th/g_tl, W = W2, fused collapse epilogue writes fp32 g_h.
// ---------------------------------------------------------------------------
template <int EPI>
__global__ __launch_bounds__(256, 2)
void gemm_kernel(const float* __restrict__ bias) {
    extern __shared__ __align__(16) __nv_bfloat16 smem[];

    const __nv_bfloat16* __restrict__ Wh = (EPI == 1) ? g_W1h : g_W2h;
    const __nv_bfloat16* __restrict__ Wl = (EPI == 1) ? g_W1l : g_W2l;
    const __nv_bfloat16* __restrict__ Ah_g = (EPI == 1) ? g_hh : g_th;
    const __nv_bfloat16* __restrict__ Al_g = (EPI == 1) ? g_hl : g_tl;

    const int tid  = threadIdx.x;
    const int lane = tid & 31;
    const int wid  = tid >> 5;
    const int wm   = wid >> 2;   // 0..1
    const int wn   = wid & 3;    // 0..3
    const int gid  = lane >> 2;  // 0..7
    const int t4   = lane & 3;   // 0..3
    const int bm0  = blockIdx.y * BM;
    const int bn0  = blockIdx.x * BN;

    // cp.async mapping: each thread copies two 16B chunks per array per stage.
    const int cr0 = tid >> 2;          // rows tid>>2 and 64+(tid>>2)
    const int cc0 = (tid & 3) * 8;     // bf16 col offset of 16B chunk

    const __nv_bfloat16* gAh0 = Ah_g + (size_t)(bm0 + cr0) * DIM + cc0;
    const __nv_bfloat16* gAl0 = Al_g + (size_t)(bm0 + cr0) * DIM + cc0;
    const __nv_bfloat16* gWh0 = Wh   + (size_t)(bn0 + cr0) * DIM + cc0;
    const __nv_bfloat16* gWl0 = Wl   + (size_t)(bn0 + cr0) * DIM + cc0;
    const size_t rstep = (size_t)64 * DIM;

    const unsigned s_base = smem_u32(smem);
    const unsigned s_off0 = (unsigned)(cr0 * ASTR + cc0) * 2u;
    const unsigned s_off1 = s_off0 + (unsigned)(64 * ASTR) * 2u;

    auto issue_stage = [&](int s) {
        const unsigned sb = s_base + (unsigned)((s % STAGES) * STAGE_BYTES);
        const int ko = s * BK;
        cp16(sb + s_off0,                  gAh0 + ko);
        cp16(sb + s_off1,                  gAh0 + rstep + ko);
        cp16(sb + TILE_BYTES + s_off0,     gAl0 + ko);
        cp16(sb + TILE_BYTES + s_off1,     gAl0 + rstep + ko);
        cp16(sb + 2 * TILE_BYTES + s_off0, gWh0 + ko);
        cp16(sb + 2 * TILE_BYTES + s_off1, gWh0 + rstep + ko);
        cp16(sb + 3 * TILE_BYTES + s_off0, gWl0 + ko);
        cp16(sb + 3 * TILE_BYTES + s_off1, gWl0 + rstep + ko);
    };

    float acc[4][4][4];
#pragma unroll
    for (int i = 0; i < 4; ++i)
#pragma unroll
        for (int j = 0; j < 4; ++j)
#pragma unroll
            for (int c = 0; c < 4; ++c) acc[i][j][c] = 0.f;

    const int NST = DIM / BK;  // 32

    // prologue: stage 0 in flight
    issue_stage(0);
    cp_commit();

    for (int s = 0; s < NST; ++s) {
        if (s + STAGES - 1 < NST) issue_stage(s + STAGES - 1);
        cp_commit();                 // exactly one group per iteration
        cp_wait<STAGES - 1>();       // stage s data resident
        __syncthreads();

        const __nv_bfloat16* Ah = smem + (size_t)(s % STAGES) * (STAGE_BYTES / 2);
        const __nv_bfloat16* Al = Ah + TILE_ELEMS;
        const __nv_bfloat16* Bh = Ah + 2 * TILE_ELEMS;
        const __nv_bfloat16* Bl = Ah + 3 * TILE_ELEMS;

#pragma unroll
        for (int kk = 0; kk < 2; ++kk) {
            unsigned afh[4][4], afl[4][4], bfh[4][2], bfl[4][2];
#pragma unroll
            for (int mi = 0; mi < 4; ++mi) {
                const int rb = (wm * 64 + mi * 16 + gid) * ASTR + kk * 16 + t4 * 2;
                afh[mi][0] = *reinterpret_cast<const unsigned*>(&Ah[rb]);
                afh[mi][1] = *reinterpret_cast<const unsigned*>(&Ah[rb + 8 * ASTR]);
                afh[mi][2] = *reinterpret_cast<const unsigned*>(&Ah[rb + 8]);
                afh[mi][3] = *reinterpret_cast<const unsigned*>(&Ah[rb + 8 * ASTR + 8]);
                afl[mi][0] = *reinterpret_cast<const unsigned*>(&Al[rb]);
                afl[mi][1] = *reinterpret_cast<const unsigned*>(&Al[rb + 8 * ASTR]);
                afl[mi][2] = *reinterpret_cast<const unsigned*>(&Al[rb + 8]);
                afl[mi][3] = *reinterpret_cast<const unsigned*>(&Al[rb + 8 * ASTR + 8]);
            }
#pragma unroll
            for (int nj = 0; nj < 4; ++nj) {
                const int cb = (wn * 32 + nj * 8 + gid) * ASTR + kk * 16 + t4 * 2;
                bfh[nj][0] = *reinterpret_cast<const unsigned*>(&Bh[cb]);
                bfh[nj][1] = *reinterpret_cast<const unsigned*>(&Bh[cb + 8]);
                bfl[nj][0] = *reinterpret_cast<const unsigned*>(&Bl[cb]);
                bfl[nj][1] = *reinterpret_cast<const unsigned*>(&Bl[cb + 8]);
            }
#pragma unroll
            for (int mi = 0; mi < 4; ++mi)
#pragma unroll
                for (int nj = 0; nj < 4; ++nj) {
                    mma16816(acc[mi][nj], afh[mi], bfh[nj]);
                    mma16816(acc[mi][nj], afh[mi], bfl[nj]);
                    mma16816(acc[mi][nj], afl[mi], bfh[nj]);
                }
        }
        if (s + 1 < NST) __syncthreads();   // reads of stage s done before re-fill
    }

    // ---- epilogue ----
#pragma unroll
    for (int mi = 0; mi < 4; ++mi) {
#pragma unroll
        for (int rr = 0; rr < 2; ++rr) {
            const int r = bm0 + wm * 64 + mi * 16 + gid + rr * 8;
            if (EPI == 1) {
                __nv_bfloat16* th = g_th + (size_t)r * DIM;
                __nv_bfloat16* tl = g_tl + (size_t)r * DIM;
#pragma unroll
                for (int nj = 0; nj < 4; ++nj) {
                    const int col = bn0 + wn * 32 + nj * 8 + t4 * 2;
                    const float v0 = tanhf(acc[mi][nj][rr * 2 + 0] + bias[col]);
                    const float v1 = tanhf(acc[mi][nj][rr * 2 + 1] + bias[col + 1]);
                    __nv_bfloat162 h2, l2;
                    split2(v0, h2.x, l2.x);
                    split2(v1, h2.y, l2.y);
                    *reinterpret_cast<__nv_bfloat162*>(th + col) = h2;
                    *reinterpret_cast<__nv_bfloat162*>(tl + col) = l2;
                }
            } else {
                const float ce = g_coef[(size_t)r * 3 + 0];
                const float cc = g_coef[(size_t)r * 3 + 1];
                const float cn = g_coef[(size_t)r * 3 + 2];
                float* hrow = g_h + (size_t)r * DIM;
#pragma unroll
                for (int nj = 0; nj < 4; ++nj) {
                    const int col = bn0 + wn * 32 + nj * 8 + t4 * 2;
                    const float2 hv = *reinterpret_cast<const float2*>(hrow + col);
                    const float2 evv = *reinterpret_cast<const float2*>(g_dirs + col);
                    const float2 cvv = *reinterpret_cast<const float2*>(g_dirs + DIM + col);
                    const float2 nvv = *reinterpret_cast<const float2*>(g_dirs + 2 * DIM + col);
                    const float2 bv  = *reinterpret_cast<const float2*>(bias + col);
                    float2 o;
                    o.x = hv.x + acc[mi][nj][rr * 2 + 0] + bv.x
                        - ce * (hv.x - evv.x) - cc * (hv.x - cvv.x) - cn * (hv.x - nvv.x);
                    o.y = hv.y + acc[mi][nj][rr * 2 + 1] + bv.y
                        - ce * (hv.y - evv.y) - cc * (hv.y - cvv.y) - cn * (hv.y - nvv.y);
                    *reinterpret_cast<float2*>(hrow + col) = o;
                }
            }
        }
    }
}

// ---------------------------------------------------------------------------
// Final norm clamp, writing to d_out.
// ---------------------------------------------------------------------------
__global__ void final_kernel(float* __restrict__ out) {
    const int row = blockIdx.x;
    const int t = threadIdx.x;
    float4 hv = reinterpret_cast<const float4*>(g_h + (size_t)row * DIM)[t];
    float s2 = dot4(hv, hv);
#pragma unroll
    for (int o = 16; o; o >>= 1) s2 += __shfl_down_sync(0xffffffffu, s2, o);
    __shared__ float sh[8];
    if ((t & 31) == 0) sh[t >> 5] = s2;
    __syncthreads();
    __shared__ float s_scale;
    if (t == 0) {
        float tot = 0.f;
#pragma unroll
        for (int i = 0; i < 8; ++i) tot += sh[i];
        float nrm = sqrtf(tot);
        s_scale = (nrm > 10.0f) ? (10.0f / (nrm + 1e-8f)) : 1.0f;
    }
    __syncthreads();
    const float sc = s_scale;
    hv.x *= sc; hv.y *= sc; hv.z *= sc; hv.w *= sc;
    reinterpret_cast<float4*>(out + (size_t)row * DIM)[t] = hv;
}

extern "C" void kernel_launch(void* const* d_in, const int* in_sizes, int n_in,
                              void* d_out, int out_size) {
    (void)in_sizes; (void)n_in; (void)out_size;
    const float* h0 = (const float*)d_in[0];
    const float* W1 = (const float*)d_in[1];
    const float* b1 = (const float*)d_in[2];
    const float* W2 = (const float*)d_in[3];
    const float* b2 = (const float*)d_in[4];
    const float* ae = (const float*)d_in[5];
    const float* ac = (const float*)d_in[6];
    const float* an = (const float*)d_in[7];
    float* out = (float*)d_out;

    static bool s_attr_done = false;
    if (!s_attr_done) {
        cudaFuncSetAttribute(gemm_kernel<1>, cudaFuncAttributeMaxDynamicSharedMemorySize, SMEM_TOTAL_BYTES);
        cudaFuncSetAttribute(gemm_kernel<2>, cudaFuncAttributeMaxDynamicSharedMemorySize, SMEM_TOTAL_BYTES);
        s_attr_done = true;
    }

    anchor_kernel<<<3, 256>>>(ae, ac, an);
    wsplit_kernel<<<DIM * DIM / 256, 256>>>(W1, W2);

    const dim3 ggrid(DIM / BN, BATCH / BM);
    for (int l = 0; l < NLAYERS; ++l) {
        if (l == 0)
            prep_kernel<<<BATCH, 256>>>(h0, /*use_ext=*/1, /*do_clamp=*/0);
        else
            prep_kernel<<<BATCH, 256>>>(nullptr, /*use_ext=*/0, /*do_clamp=*/1);
        gemm_kernel<1><<<ggrid, 256, SMEM_TOTAL_BYTES>>>(b1);
        gemm_kernel<2><<<ggrid, 256, SMEM_TOTAL_BYTES>>>(b2);
    }
    final_kernel<<<BATCH, 256>>>(out);
}

// round 8
// speedup vs baseline: 2.7387x; 1.2061x over previous
#include <cuda_runtime.h>
#include <cuda_bf16.h>
#include <math.h>

#define BATCH 16384
#define DIM   1024
#define NLAYERS 6

#define BM 128
#define BN 128
#define BK 32
#define ASTR 40            // smem row stride (bf16): 32 + 8 pad; 80B rows, 16B-aligned, LDSM conflict-free
#define STAGES 2
#define TILE_ELEMS (BM * ASTR)
#define TILE_BYTES (TILE_ELEMS * 2)
#define STAGE_BYTES (4 * TILE_BYTES)
#define SMEM_TOTAL_BYTES (STAGES * STAGE_BYTES)  // 81920 B -> 2 CTAs/SM

// ---- scratch (allocation-free: __device__ globals; device-code refs only) ----
__device__ float g_h[(size_t)BATCH * DIM];
__device__ __nv_bfloat16 g_hh[(size_t)BATCH * DIM];
__device__ __nv_bfloat16 g_hl[(size_t)BATCH * DIM];
__device__ __nv_bfloat16 g_th[(size_t)BATCH * DIM];
__device__ __nv_bfloat16 g_tl[(size_t)BATCH * DIM];
__device__ __nv_bfloat16 g_W1h[DIM * DIM], g_W1l[DIM * DIM];
__device__ __nv_bfloat16 g_W2h[DIM * DIM], g_W2l[DIM * DIM];
__device__ float g_dirs[3 * DIM];
__device__ float g_dn2[3];
__device__ float g_coef[(size_t)BATCH * 3];

static __device__ __forceinline__ float dot4(const float4 a, const float4 b) {
    return a.x * b.x + a.y * b.y + a.z * b.z + a.w * b.w;
}

static __device__ __forceinline__ void split2(float x, __nv_bfloat16& h, __nv_bfloat16& l) {
    h = __float2bfloat16(x);
    l = __float2bfloat16(x - __bfloat162float(h));
}

static __device__ __forceinline__ void mma16816(float* c, const unsigned* a, const unsigned* b) {
    asm volatile(
        "mma.sync.aligned.m16n8k16.row.col.f32.bf16.bf16.f32 "
        "{%0,%1,%2,%3}, {%4,%5,%6,%7}, {%8,%9}, {%0,%1,%2,%3};\n"
        : "+f"(c[0]), "+f"(c[1]), "+f"(c[2]), "+f"(c[3])
        : "r"(a[0]), "r"(a[1]), "r"(a[2]), "r"(a[3]), "r"(b[0]), "r"(b[1]));
}

#define LDSM_X4(r, a) \
    asm volatile("ldmatrix.sync.aligned.m8n8.x4.shared.b16 {%0,%1,%2,%3}, [%4];" \
        : "=r"((r)[0]), "=r"((r)[1]), "=r"((r)[2]), "=r"((r)[3]) : "r"(a))

static __device__ __forceinline__ unsigned smem_u32(const void* p) {
    return (unsigned)__cvta_generic_to_shared(p);
}

static __device__ __forceinline__ void cp16(unsigned dst, const void* src) {
    asm volatile("cp.async.cg.shared.global [%0], [%1], 16;\n" :: "r"(dst), "l"(src));
}
static __device__ __forceinline__ void cp_commit() {
    asm volatile("cp.async.commit_group;\n");
}
template <int N>
static __device__ __forceinline__ void cp_wait() {
    asm volatile("cp.async.wait_group %0;\n" :: "n"(N));
}

// ---------------------------------------------------------------------------
__global__ void wsplit_kernel(const float* __restrict__ W1, const float* __restrict__ W2) {
    const size_t i = (size_t)blockIdx.x * 256 + threadIdx.x;
    float x = W1[i];
    split2(x, g_W1h[i], g_W1l[i]);
    x = W2[i];
    split2(x, g_W2h[i], g_W2l[i]);
}

__global__ void anchor_kernel(const float* __restrict__ ae,
                              const float* __restrict__ ac,
                              const float* __restrict__ an) {
    const int b = blockIdx.x;
    const int t = threadIdx.x;
    const float* src = (b == 0) ? ae : ((b == 1) ? ac : an);
    float4 v = reinterpret_cast<const float4*>(src)[t];
    float s = dot4(v, v);
#pragma unroll
    for (int o = 16; o; o >>= 1) s += __shfl_down_sync(0xffffffffu, s, o);
    __shared__ float sh[8];
    if ((t & 31) == 0) sh[t >> 5] = s;
    __syncthreads();
    __shared__ float s_inv;
    if (t == 0) {
        float tot = 0.f;
#pragma unroll
        for (int i = 0; i < 8; ++i) tot += sh[i];
        s_inv = 1.0f / fmaxf(sqrtf(tot), 1e-12f);
    }
    __syncthreads();
    const float inv = s_inv;
    v.x *= inv; v.y *= inv; v.z *= inv; v.w *= inv;
    reinterpret_cast<float4*>(g_dirs + (size_t)b * DIM)[t] = v;

    float s2 = dot4(v, v);
#pragma unroll
    for (int o = 16; o; o >>= 1) s2 += __shfl_down_sync(0xffffffffu, s2, o);
    __syncthreads();
    if ((t & 31) == 0) sh[t >> 5] = s2;
    __syncthreads();
    if (t == 0) {
        float tot = 0.f;
#pragma unroll
        for (int i = 0; i < 8; ++i) tot += sh[i];
        g_dn2[b] = tot;
    }
}

// ---------------------------------------------------------------------------
// Warp-per-row prep: shfl_xor reductions only (no smem/barriers).
// 256 threads = 8 rows per block; grid = BATCH/8.
// ---------------------------------------------------------------------------
__global__ void prep_kernel(const float* __restrict__ Hext, int use_ext, int do_clamp) {
    const int row  = (blockIdx.x * 256 + threadIdx.x) >> 5;
    const int lane = threadIdx.x & 31;
    const float* hrow = use_ext ? (Hext + (size_t)row * DIM) : (g_h + (size_t)row * DIM);

    float4 hv[8];
    float s2 = 0.f, de = 0.f, dc = 0.f, dn = 0.f;
#pragma unroll
    for (int j = 0; j < 8; ++j) {
        const int idx = lane + j * 32;
        hv[j] = reinterpret_cast<const float4*>(hrow)[idx];
        const float4 ev = reinterpret_cast<const float4*>(g_dirs)[idx];
        const float4 cv = reinterpret_cast<const float4*>(g_dirs + DIM)[idx];
        const float4 nv = reinterpret_cast<const float4*>(g_dirs + 2 * DIM)[idx];
        s2 += dot4(hv[j], hv[j]);
        de += dot4(hv[j], ev);
        dc += dot4(hv[j], cv);
        dn += dot4(hv[j], nv);
    }
#pragma unroll
    for (int o = 16; o; o >>= 1) {
        s2 += __shfl_xor_sync(0xffffffffu, s2, o);
        de += __shfl_xor_sync(0xffffffffu, de, o);
        dc += __shfl_xor_sync(0xffffffffu, dc, o);
        dn += __shfl_xor_sync(0xffffffffu, dn, o);
    }

    float scale = 1.0f;
    if (do_clamp) {
        const float nrm = sqrtf(s2);
        if (nrm > 10.0f) scale = 10.0f / (nrm + 1e-8f);
    }
    const float S2 = s2 * scale * scale;
    const float DE = de * scale, DC = dc * scale, DN = dn * scale;

    if (lane == 0) {
        const float hn = fmaxf(sqrtf(S2), 1e-12f);
        const float a_e = DE / hn, a_c = DC / hn, a_n = DN / hn;
        const float div_e = 1.0f - a_e, div_c = 1.0f - a_c, div_n = 1.0f - a_n;
        const float boundary = fminf(fmaxf(1.0f - fabsf(a_e - a_c), 0.0f), 1.0f);
        const float fe = fmaxf(sqrtf(fmaxf(S2 - 2.0f * DE + g_dn2[0], 0.0f)), 1e-12f);
        const float fc = fmaxf(sqrtf(fmaxf(S2 - 2.0f * DC + g_dn2[1], 0.0f)), 1e-12f);
        const float fn = fmaxf(sqrtf(fmaxf(S2 - 2.0f * DN + g_dn2[2], 0.0f)), 1e-12f);
        g_coef[(size_t)row * 3 + 0] = 0.1f  * div_e / fe;
        g_coef[(size_t)row * 3 + 1] = 0.1f  * div_c / fc;
        g_coef[(size_t)row * 3 + 2] = (0.05f * div_n + 0.05f * boundary) / fn;
    }

    const bool store_h = (use_ext != 0) || (scale != 1.0f);
#pragma unroll
    for (int j = 0; j < 8; ++j) {
        const int idx = lane + j * 32;
        float4 v = hv[j];
        v.x *= scale; v.y *= scale; v.z *= scale; v.w *= scale;
        if (store_h) reinterpret_cast<float4*>(g_h + (size_t)row * DIM)[idx] = v;
        __nv_bfloat16 hh[4], hl[4];
        split2(v.x, hh[0], hl[0]);
        split2(v.y, hh[1], hl[1]);
        split2(v.z, hh[2], hl[2]);
        split2(v.w, hh[3], hl[3]);
        reinterpret_cast<uint2*>(g_hh + (size_t)row * DIM)[idx] = *reinterpret_cast<uint2*>(hh);
        reinterpret_cast<uint2*>(g_hl + (size_t)row * DIM)[idx] = *reinterpret_cast<uint2*>(hl);
    }
}

// ---------------------------------------------------------------------------
// Tensor-core NT GEMM, bf16x3, cp.async 2-stage, 2 CTAs/SM, ldmatrix loads.
// ---------------------------------------------------------------------------
template <int EPI>
__global__ __launch_bounds__(256, 2)
void gemm_kernel(const float* __restrict__ bias) {
    extern __shared__ __align__(16) __nv_bfloat16 smem[];

    const __nv_bfloat16* __restrict__ Wh   = (EPI == 1) ? g_W1h : g_W2h;
    const __nv_bfloat16* __restrict__ Wl   = (EPI == 1) ? g_W1l : g_W2l;
    const __nv_bfloat16* __restrict__ Ah_g = (EPI == 1) ? g_hh : g_th;
    const __nv_bfloat16* __restrict__ Al_g = (EPI == 1) ? g_hl : g_tl;

    const int tid  = threadIdx.x;
    const int lane = tid & 31;
    const int wid  = tid >> 5;
    const int wm   = wid >> 2;
    const int wn   = wid & 3;
    const int gid  = lane >> 2;
    const int t4   = lane & 3;
    const int bm0  = blockIdx.y * BM;
    const int bn0  = blockIdx.x * BN;

    const int cr0 = tid >> 2;
    const int cc0 = (tid & 3) * 8;

    const __nv_bfloat16* gAh0 = Ah_g + (size_t)(bm0 + cr0) * DIM + cc0;
    const __nv_bfloat16* gAl0 = Al_g + (size_t)(bm0 + cr0) * DIM + cc0;
    const __nv_bfloat16* gWh0 = Wh   + (size_t)(bn0 + cr0) * DIM + cc0;
    const __nv_bfloat16* gWl0 = Wl   + (size_t)(bn0 + cr0) * DIM + cc0;
    const size_t rstep = (size_t)64 * DIM;

    const unsigned s_base = smem_u32(smem);
    const unsigned s_off0 = (unsigned)(cr0 * ASTR + cc0) * 2u;
    const unsigned s_off1 = s_off0 + (unsigned)(64 * ASTR) * 2u;

    auto issue_stage = [&](int s) {
        const unsigned sb = s_base + (unsigned)((s % STAGES) * STAGE_BYTES);
        const int ko = s * BK;
        cp16(sb + s_off0,                  gAh0 + ko);
        cp16(sb + s_off1,                  gAh0 + rstep + ko);
        cp16(sb + TILE_BYTES + s_off0,     gAl0 + ko);
        cp16(sb + TILE_BYTES + s_off1,     gAl0 + rstep + ko);
        cp16(sb + 2 * TILE_BYTES + s_off0, gWh0 + ko);
        cp16(sb + 2 * TILE_BYTES + s_off1, gWh0 + rstep + ko);
        cp16(sb + 3 * TILE_BYTES + s_off0, gWl0 + ko);
        cp16(sb + 3 * TILE_BYTES + s_off1, gWl0 + rstep + ko);
    };

    // ldmatrix per-lane address components
    const int rA = wm * 64 + (lane & 15);           // A row for this lane
    const int cA = (lane >> 4) * 8;                 // A k-offset (elements)
    const int rB = wn * 32 + (lane >> 4) * 8 + (lane & 7);  // B row (n) for this lane
    const int cB = ((lane >> 3) & 1) * 8;           // B k-offset

    float acc[4][4][4];
#pragma unroll
    for (int i = 0; i < 4; ++i)
#pragma unroll
        for (int j = 0; j < 4; ++j)
#pragma unroll
            for (int c = 0; c < 4; ++c) acc[i][j][c] = 0.f;

    const int NST = DIM / BK;  // 32

    issue_stage(0);
    cp_commit();

    for (int s = 0; s < NST; ++s) {
        if (s + STAGES - 1 < NST) issue_stage(s + STAGES - 1);
        cp_commit();
        cp_wait<STAGES - 1>();
        __syncthreads();

        const unsigned ab = s_base + (unsigned)((s % STAGES) * STAGE_BYTES);
        const unsigned uAh = ab;
        const unsigned uAl = ab + TILE_BYTES;
        const unsigned uBh = ab + 2 * TILE_BYTES;
        const unsigned uBl = ab + 3 * TILE_BYTES;

#pragma unroll
        for (int kk = 0; kk < 2; ++kk) {
            unsigned afh[4][4], afl[4][4], bfh[4][2], bfl[4][2];
#pragma unroll
            for (int mi = 0; mi < 4; ++mi) {
                const unsigned off = (unsigned)(((rA + mi * 16) * ASTR) + kk * 16 + cA) * 2u;
                LDSM_X4(afh[mi], uAh + off);
                LDSM_X4(afl[mi], uAl + off);
            }
#pragma unroll
            for (int p = 0; p < 2; ++p) {
                const unsigned off = (unsigned)(((rB + p * 16) * ASTR) + kk * 16 + cB) * 2u;
                unsigned rh[4], rl[4];
                LDSM_X4(rh, uBh + off);
                LDSM_X4(rl, uBl + off);
                bfh[2 * p][0] = rh[0]; bfh[2 * p][1] = rh[1];
                bfh[2 * p + 1][0] = rh[2]; bfh[2 * p + 1][1] = rh[3];
                bfl[2 * p][0] = rl[0]; bfl[2 * p][1] = rl[1];
                bfl[2 * p + 1][0] = rl[2]; bfl[2 * p + 1][1] = rl[3];
            }
#pragma unroll
            for (int mi = 0; mi < 4; ++mi)
#pragma unroll
                for (int nj = 0; nj < 4; ++nj) {
                    mma16816(acc[mi][nj], afh[mi], bfh[nj]);
                    mma16816(acc[mi][nj], afh[mi], bfl[nj]);
                    mma16816(acc[mi][nj], afl[mi], bfh[nj]);
                }
        }
        if (s + 1 < NST) __syncthreads();
    }

    // ---- epilogue ----
#pragma unroll
    for (int mi = 0; mi < 4; ++mi) {
#pragma unroll
        for (int rr = 0; rr < 2; ++rr) {
            const int r = bm0 + wm * 64 + mi * 16 + gid + rr * 8;
            if (EPI == 1) {
                __nv_bfloat16* th = g_th + (size_t)r * DIM;
                __nv_bfloat16* tl = g_tl + (size_t)r * DIM;
#pragma unroll
                for (int nj = 0; nj < 4; ++nj) {
                    const int col = bn0 + wn * 32 + nj * 8 + t4 * 2;
                    const float v0 = tanhf(acc[mi][nj][rr * 2 + 0] + bias[col]);
                    const float v1 = tanhf(acc[mi][nj][rr * 2 + 1] + bias[col + 1]);
                    __nv_bfloat162 h2, l2;
                    split2(v0, h2.x, l2.x);
                    split2(v1, h2.y, l2.y);
                    *reinterpret_cast<__nv_bfloat162*>(th + col) = h2;
                    *reinterpret_cast<__nv_bfloat162*>(tl + col) = l2;
                }
            } else {
                const float ce = g_coef[(size_t)r * 3 + 0];
                const float cc = g_coef[(size_t)r * 3 + 1];
                const float cn = g_coef[(size_t)r * 3 + 2];
                float* hrow = g_h + (size_t)r * DIM;
#pragma unroll
                for (int nj = 0; nj < 4; ++nj) {
                    const int col = bn0 + wn * 32 + nj * 8 + t4 * 2;
                    const float2 hv = *reinterpret_cast<const float2*>(hrow + col);
                    const float2 evv = *reinterpret_cast<const float2*>(g_dirs + col);
                    const float2 cvv = *reinterpret_cast<const float2*>(g_dirs + DIM + col);
                    const float2 nvv = *reinterpret_cast<const float2*>(g_dirs + 2 * DIM + col);
                    const float2 bv  = *reinterpret_cast<const float2*>(bias + col);
                    float2 o;
                    o.x = hv.x + acc[mi][nj][rr * 2 + 0] + bv.x
                        - ce * (hv.x - evv.x) - cc * (hv.x - cvv.x) - cn * (hv.x - nvv.x);
                    o.y = hv.y + acc[mi][nj][rr * 2 + 1] + bv.y
                        - ce * (hv.y - evv.y) - cc * (hv.y - cvv.y) - cn * (hv.y - nvv.y);
                    *reinterpret_cast<float2*>(hrow + col) = o;
                }
            }
        }
    }
}

// ---------------------------------------------------------------------------
// Warp-per-row final norm clamp -> d_out.
// ---------------------------------------------------------------------------
__global__ void final_kernel(float* __restrict__ out) {
    const int row  = (blockIdx.x * 256 + threadIdx.x) >> 5;
    const int lane = threadIdx.x & 31;
    float4 hv[8];
    float s2 = 0.f;
#pragma unroll
    for (int j = 0; j < 8; ++j) {
        hv[j] = reinterpret_cast<const float4*>(g_h + (size_t)row * DIM)[lane + j * 32];
        s2 += dot4(hv[j], hv[j]);
    }
#pragma unroll
    for (int o = 16; o; o >>= 1) s2 += __shfl_xor_sync(0xffffffffu, s2, o);
    const float nrm = sqrtf(s2);
    const float sc = (nrm > 10.0f) ? (10.0f / (nrm + 1e-8f)) : 1.0f;
#pragma unroll
    for (int j = 0; j < 8; ++j) {
        float4 v = hv[j];
        v.x *= sc; v.y *= sc; v.z *= sc; v.w *= sc;
        reinterpret_cast<float4*>(out + (size_t)row * DIM)[lane + j * 32] = v;
    }
}

extern "C" void kernel_launch(void* const* d_in, const int* in_sizes, int n_in,
                              void* d_out, int out_size) {
    (void)in_sizes; (void)n_in; (void)out_size;
    const float* h0 = (const float*)d_in[0];
    const float* W1 = (const float*)d_in[1];
    const float* b1 = (const float*)d_in[2];
    const float* W2 = (const float*)d_in[3];
    const float* b2 = (const float*)d_in[4];
    const float* ae = (const float*)d_in[5];
    const float* ac = (const float*)d_in[6];
    const float* an = (const float*)d_in[7];
    float* out = (float*)d_out;

    static bool s_attr_done = false;
    if (!s_attr_done) {
        cudaFuncSetAttribute(gemm_kernel<1>, cudaFuncAttributeMaxDynamicSharedMemorySize, SMEM_TOTAL_BYTES);
        cudaFuncSetAttribute(gemm_kernel<2>, cudaFuncAttributeMaxDynamicSharedMemorySize, SMEM_TOTAL_BYTES);
        s_attr_done = true;
    }

    anchor_kernel<<<3, 256>>>(ae, ac, an);
    wsplit_kernel<<<DIM * DIM / 256, 256>>>(W1, W2);

    const dim3 ggrid(DIM / BN, BATCH / BM);
    for (int l = 0; l < NLAYERS; ++l) {
        if (l == 0)
            prep_kernel<<<BATCH / 8, 256>>>(h0, /*use_ext=*/1, /*do_clamp=*/0);
        else
            prep_kernel<<<BATCH / 8, 256>>>(nullptr, /*use_ext=*/0, /*do_clamp=*/1);
        gemm_kernel<1><<<ggrid, 256, SMEM_TOTAL_BYTES>>>(b1);
        gemm_kernel<2><<<ggrid, 256, SMEM_TOTAL_BYTES>>>(b2);
    }
    final_kernel<<<BATCH / 8, 256>>>(out);
}